// round 1
// baseline (speedup 1.0000x reference)
#include <cuda_runtime.h>
#include <cuda_bf16.h>
#include <math.h>

// Problem constants
#define BB 64
#define TT 512
#define DD 512
#define HH 8
#define DHH 64

// ---------------- scratch (device globals; allocation-free) ----------------
__device__ float g_qin[BB * TT * DD];
__device__ float g_kin[BB * TT * DD];
__device__ float g_qp [BB * TT * DD];
__device__ float g_kp [BB * TT * DD];
__device__ float g_vp [BB * TT * DD];
__device__ float g_res[BB * TT * DD];
__device__ float g_hid[BB * TT * 4 * DD];
__device__ float g_res2[BB * TT * DD];

// ---------------- kernel 1: positional encoding add ----------------
__global__ void addpe_kernel(const float* __restrict__ q, const float* __restrict__ k,
                             float* __restrict__ qo, float* __restrict__ ko) {
    int idx = blockIdx.x * blockDim.x + threadIdx.x;
    if (idx >= BB * TT * DD) return;
    int d = idx % DD;
    int t = (idx / DD) % TT;
    int j = (d < DD / 2) ? d : d - DD / 2;
    // inv_freq = 10000^(-2j/D)
    float invf = expf(-(2.0f * (float)j / (float)DD) * 9.210340371976184f); // ln(10000)
    float arg = (float)t * invf;
    float pe = (d < DD / 2) ? cosf(arg) : sinf(arg);
    qo[idx] = q[idx] + pe;
    ko[idx] = k[idx] + pe;
}

// ---------------- kernel 2: tiled fp32 SGEMM, C = [Src +] [relu](A @ W) ----------------
// A: MxK row-major, W: KxN row-major, C: MxN. M%128==0, N%128==0, K%8==0.
template<bool RELU, bool ADD>
__global__ void sgemm_kernel(const float* __restrict__ A, const float* __restrict__ W,
                             const float* __restrict__ Src, float* __restrict__ C,
                             int M, int N, int K) {
    const int BM = 128, BN = 128, BK = 8, TM = 8, TN = 8;
    __shared__ float As[BK][BM];   // transposed A tile
    __shared__ float Bs[BK][BN];

    int tid = threadIdx.x;                 // 256 threads
    int bm = blockIdx.y * BM;
    int bn = blockIdx.x * BN;

    int aRow = tid >> 1;                   // 0..127
    int aCol = (tid & 1) * 4;              // 0 or 4
    int bRow = tid >> 5;                   // 0..7
    int bCol = (tid & 31) * 4;             // 0..124

    int ty = (tid >> 4) * TM;              // 0..120
    int tx = (tid & 15) * TN;

    float acc[TM][TN];
    #pragma unroll
    for (int i = 0; i < TM; i++)
        #pragma unroll
        for (int j = 0; j < TN; j++) acc[i][j] = 0.0f;

    for (int k0 = 0; k0 < K; k0 += BK) {
        float4 av = *(const float4*)(A + (size_t)(bm + aRow) * K + k0 + aCol);
        As[aCol + 0][aRow] = av.x;
        As[aCol + 1][aRow] = av.y;
        As[aCol + 2][aRow] = av.z;
        As[aCol + 3][aRow] = av.w;
        float4 bv = *(const float4*)(W + (size_t)(k0 + bRow) * N + bn + bCol);
        *(float4*)&Bs[bRow][bCol] = bv;
        __syncthreads();

        #pragma unroll
        for (int k = 0; k < BK; k++) {
            float ra[TM], rb[TN];
            #pragma unroll
            for (int i = 0; i < TM; i++) ra[i] = As[k][ty + i];
            #pragma unroll
            for (int j = 0; j < TN; j++) rb[j] = Bs[k][tx + j];
            #pragma unroll
            for (int i = 0; i < TM; i++)
                #pragma unroll
                for (int j = 0; j < TN; j++)
                    acc[i][j] = fmaf(ra[i], rb[j], acc[i][j]);
        }
        __syncthreads();
    }

    #pragma unroll
    for (int i = 0; i < TM; i++) {
        size_t row = (size_t)(bm + ty + i);
        #pragma unroll
        for (int j = 0; j < TN; j += 4) {
            float4 v = make_float4(acc[i][j], acc[i][j+1], acc[i][j+2], acc[i][j+3]);
            if (RELU) {
                v.x = fmaxf(v.x, 0.0f); v.y = fmaxf(v.y, 0.0f);
                v.z = fmaxf(v.z, 0.0f); v.w = fmaxf(v.w, 0.0f);
            }
            if (ADD) {
                float4 s = *(const float4*)(Src + row * N + bn + tx + j);
                v.x += s.x; v.y += s.y; v.z += s.z; v.w += s.w;
            }
            *(float4*)(C + row * N + bn + tx + j) = v;
        }
    }
}

// ---------------- kernel 3: masked multi-head attention + residual ----------------
// grid: (T/TQ, H, B), block: 256. Computes res[b,t, h*64..] = attn_out + q_in.
#define TQ 16
#define TSS 32
__global__ void attn_kernel(const float* __restrict__ qp, const float* __restrict__ kp,
                            const float* __restrict__ vp, const float* __restrict__ qin,
                            const int* __restrict__ qlens, const int* __restrict__ klens,
                            float* __restrict__ res) {
    __shared__ float sc[TQ][513];     // scores / probs, padded stride
    __shared__ float qs[TQ][65];
    __shared__ float kv[TSS][65];

    int b = blockIdx.z, h = blockIdx.y;
    int t0 = blockIdx.x * TQ;
    int tid = threadIdx.x;
    int klen = klens[b];
    int qlen = qlens[b];
    size_t base = ((size_t)b * TT) * DD + h * DHH;

    // load Q tile (16 x 64): one float4 per thread
    {
        int e = tid * 4;
        int qi = e / DHH, k = e % DHH;
        float4 v = *(const float4*)(qp + base + (size_t)(t0 + qi) * DD + k);
        qs[qi][k] = v.x; qs[qi][k+1] = v.y; qs[qi][k+2] = v.z; qs[qi][k+3] = v.w;
    }

    // scores
    int sj = tid & (TSS - 1);
    int qi0 = (tid >> 5) * 2;
    for (int s0 = 0; s0 < TT; s0 += TSS) {
        __syncthreads();  // q tile ready / prior readers of kv done
        #pragma unroll
        for (int u = 0; u < 2; u++) {
            int e = (tid + u * 256) * 4;
            int si = e / DHH, k = e % DHH;
            float4 v = *(const float4*)(kp + base + (size_t)(s0 + si) * DD + k);
            kv[si][k] = v.x; kv[si][k+1] = v.y; kv[si][k+2] = v.z; kv[si][k+3] = v.w;
        }
        __syncthreads();
        #pragma unroll
        for (int u = 0; u < 2; u++) {
            int qi = qi0 + u;
            float acc = 0.0f;
            #pragma unroll
            for (int k = 0; k < DHH; k++) acc = fmaf(qs[qi][k], kv[sj][k], acc);
            int s = s0 + sj;
            sc[qi][s] = (s < klen) ? acc * 0.125f : -3.0e38f;
        }
    }
    __syncthreads();

    // softmax per row (warp per row, 2 rows per warp)
    int warp = tid >> 5, lane = tid & 31;
    for (int r = warp; r < TQ; r += 8) {
        float m = -3.0e38f;
        for (int s = lane; s < TT; s += 32) m = fmaxf(m, sc[r][s]);
        #pragma unroll
        for (int o = 16; o > 0; o >>= 1) m = fmaxf(m, __shfl_xor_sync(0xffffffffu, m, o));
        float sum = 0.0f;
        for (int s = lane; s < TT; s += 32) {
            float e = expf(sc[r][s] - m);
            sc[r][s] = e;
            sum += e;
        }
        #pragma unroll
        for (int o = 16; o > 0; o >>= 1) sum += __shfl_xor_sync(0xffffffffu, sum, o);
        float inv = 1.0f / sum;
        for (int s = lane; s < TT; s += 32) sc[r][s] *= inv;
    }

    // AV: each thread owns 4 outputs: row qi = tid/16, cols dk..dk+3
    int qi = tid >> 4;
    int dk = (tid & 15) * 4;
    float acc0 = 0, acc1 = 0, acc2 = 0, acc3 = 0;
    for (int s0 = 0; s0 < TT; s0 += TSS) {
        __syncthreads();   // probs visible (first iter) / prior kv readers done
        #pragma unroll
        for (int u = 0; u < 2; u++) {
            int e = (tid + u * 256) * 4;
            int si = e / DHH, k = e % DHH;
            float4 v = *(const float4*)(vp + base + (size_t)(s0 + si) * DD + k);
            kv[si][k] = v.x; kv[si][k+1] = v.y; kv[si][k+2] = v.z; kv[si][k+3] = v.w;
        }
        __syncthreads();
        #pragma unroll
        for (int s = 0; s < TSS; s++) {
            float a = sc[qi][s0 + s];
            acc0 = fmaf(a, kv[s][dk],     acc0);
            acc1 = fmaf(a, kv[s][dk + 1], acc1);
            acc2 = fmaf(a, kv[s][dk + 2], acc2);
            acc3 = fmaf(a, kv[s][dk + 3], acc3);
        }
    }

    int t = t0 + qi;
    bool valid = (t < qlen);   // q_mask zeroes attention output for t >= qlen
    size_t off = base + (size_t)t * DD + dk;
    float4 r;
    r.x = qin[off + 0] + (valid ? acc0 : 0.0f);
    r.y = qin[off + 1] + (valid ? acc1 : 0.0f);
    r.z = qin[off + 2] + (valid ? acc2 : 0.0f);
    r.w = qin[off + 3] + (valid ? acc3 : 0.0f);
    *(float4*)(res + off) = r;
}

// ---------------- kernel 4: mean over T ----------------
__global__ void mean_kernel(const float* __restrict__ x, float* __restrict__ out) {
    int d = blockIdx.x * blockDim.x + threadIdx.x;   // 0..511
    int b = blockIdx.y;
    if (d >= DD) return;
    float s = 0.0f;
    const float* p = x + ((size_t)b * TT) * DD + d;
    for (int t = 0; t < TT; t++) s += p[(size_t)t * DD];
    out[b * DD + d] = s * (1.0f / (float)TT);
}

// ---------------- launch ----------------
extern "C" void kernel_launch(void* const* d_in, const int* in_sizes, int n_in,
                              void* d_out, int out_size) {
    const float* queries = (const float*)d_in[0];
    const float* keys    = (const float*)d_in[1];
    const int*   qlens   = (const int*)d_in[2];
    const int*   klens   = (const int*)d_in[3];
    const float* W_Q     = (const float*)d_in[4];
    const float* W_K     = (const float*)d_in[5];
    const float* W_V     = (const float*)d_in[6];
    const float* fw1     = (const float*)d_in[7];
    const float* fw2     = (const float*)d_in[8];
    float* out = (float*)d_out;

    float *qin, *kin, *qp, *kp, *vp, *resb, *hid, *res2;
    cudaGetSymbolAddress((void**)&qin,  g_qin);
    cudaGetSymbolAddress((void**)&kin,  g_kin);
    cudaGetSymbolAddress((void**)&qp,   g_qp);
    cudaGetSymbolAddress((void**)&kp,   g_kp);
    cudaGetSymbolAddress((void**)&vp,   g_vp);
    cudaGetSymbolAddress((void**)&resb, g_res);
    cudaGetSymbolAddress((void**)&hid,  g_hid);
    cudaGetSymbolAddress((void**)&res2, g_res2);

    const int M = BB * TT;          // 32768
    const int n_elem = BB * TT * DD;

    // 1. positional encoding
    addpe_kernel<<<(n_elem + 255) / 256, 256>>>(queries, keys, qin, kin);

    // 2-4. projections
    dim3 gproj(DD / 128, M / 128);
    sgemm_kernel<false, false><<<gproj, 256>>>(qin, W_Q, nullptr, qp, M, DD, DD);
    sgemm_kernel<false, false><<<gproj, 256>>>(kin, W_K, nullptr, kp, M, DD, DD);
    // DeepCTR quirk: V projected from already-projected keys
    sgemm_kernel<false, false><<<gproj, 256>>>(kp, W_V, nullptr, vp, M, DD, DD);

    // 5. attention + residual(q_in)
    dim3 gattn(TT / TQ, HH, BB);
    attn_kernel<<<gattn, 256>>>(qp, kp, vp, qin, qlens, klens, resb);

    // 6. FFN layer 1: hid = relu(res @ fw1), N = 2048
    dim3 gff1((4 * DD) / 128, M / 128);
    sgemm_kernel<true, false><<<gff1, 256>>>(resb, fw1, nullptr, hid, M, 4 * DD, DD);

    // 7. FFN layer 2 + residual: res2 = res + hid @ fw2
    dim3 gff2(DD / 128, M / 128);
    sgemm_kernel<false, true><<<gff2, 256>>>(hid, fw2, resb, res2, M, DD, 4 * DD);

    // 8. mean over T -> (B, 1, D)
    dim3 gmean(DD / 128, BB);
    mean_kernel<<<gmean, 128>>>(res2, out);
}

// round 2
// speedup vs baseline: 1.6308x; 1.6308x over previous
#include <cuda_runtime.h>
#include <cuda_bf16.h>
#include <math.h>
#include <stdint.h>

// Problem constants
#define BB 64
#define TT 512
#define DD 512
#define HH 8
#define DHH 64

// ---------------- scratch (device globals; allocation-free) ----------------
__device__ float g_qin[BB * TT * DD];
__device__ float g_kin[BB * TT * DD];
__device__ float g_qp [BB * TT * DD];
__device__ float g_kp [BB * TT * DD];
__device__ float g_vp [BB * TT * DD];
__device__ float g_res[BB * TT * DD];
__device__ float g_hid[BB * TT * 4 * DD];
__device__ float g_res2[BB * TT * DD];

// ---------------- kernel 1: positional encoding add ----------------
__global__ void addpe_kernel(const float* __restrict__ q, const float* __restrict__ k,
                             float* __restrict__ qo, float* __restrict__ ko) {
    int idx = blockIdx.x * blockDim.x + threadIdx.x;
    if (idx >= BB * TT * DD) return;
    int d = idx % DD;
    int t = (idx / DD) % TT;
    int j = (d < DD / 2) ? d : d - DD / 2;
    float invf = expf(-(2.0f * (float)j / (float)DD) * 9.210340371976184f); // ln(10000)
    float arg = (float)t * invf;
    float pe = (d < DD / 2) ? cosf(arg) : sinf(arg);
    qo[idx] = q[idx] + pe;
    ko[idx] = k[idx] + pe;
}

// ---------------- TF32 tensor-core GEMM ----------------
// C = [Src +] [relu](A @ W).  A: MxK row-major, W: KxN row-major.
// Block tile 128x128x32, 8 warps (2x4), warp tile 64x32 via m16n8k8 tf32 mma.
__device__ __forceinline__ uint32_t f2tf32(float x) {
    uint32_t r;
    asm("cvt.rna.tf32.f32 %0, %1;" : "=r"(r) : "f"(x));
    return r;
}

template<bool RELU, bool ADD>
__global__ __launch_bounds__(256) void tf32_gemm_kernel(
        const float* __restrict__ A, const float* __restrict__ W,
        const float* __restrict__ Src, float* __restrict__ C,
        int M, int N, int K) {
    const int BM = 128, BN = 128, BK = 32;
    __shared__ uint32_t As[BM][BK + 4];   // pad 4: conflict-free frag loads
    __shared__ uint32_t Bs[BK][BN + 4];

    int tid = threadIdx.x;
    int lane = tid & 31;
    int warp = tid >> 5;
    int wr = (warp >> 2) * 64;    // warp row base within block tile
    int wc = (warp & 3) * 32;     // warp col base
    int bm = blockIdx.y * BM;
    int bn = blockIdx.x * BN;
    int g = lane >> 2;            // group id 0..7
    int q = lane & 3;             // thread-in-group 0..3

    float acc[4][4][4];
    #pragma unroll
    for (int mi = 0; mi < 4; mi++)
        #pragma unroll
        for (int ni = 0; ni < 4; ni++)
            #pragma unroll
            for (int r = 0; r < 4; r++) acc[mi][ni][r] = 0.0f;

    for (int k0 = 0; k0 < K; k0 += BK) {
        // load A tile: 128x32 floats = 1024 float4, 4 per thread
        #pragma unroll
        for (int i = 0; i < 4; i++) {
            int c = tid + i * 256;
            int row = c >> 3;
            int col = (c & 7) * 4;
            float4 v = *(const float4*)(A + (size_t)(bm + row) * K + k0 + col);
            As[row][col + 0] = f2tf32(v.x);
            As[row][col + 1] = f2tf32(v.y);
            As[row][col + 2] = f2tf32(v.z);
            As[row][col + 3] = f2tf32(v.w);
        }
        // load B tile: 32x128
        #pragma unroll
        for (int i = 0; i < 4; i++) {
            int c = tid + i * 256;
            int kr = c >> 5;
            int col = (c & 31) * 4;
            float4 v = *(const float4*)(W + (size_t)(k0 + kr) * N + bn + col);
            Bs[kr][col + 0] = f2tf32(v.x);
            Bs[kr][col + 1] = f2tf32(v.y);
            Bs[kr][col + 2] = f2tf32(v.z);
            Bs[kr][col + 3] = f2tf32(v.w);
        }
        __syncthreads();

        #pragma unroll
        for (int kk = 0; kk < BK; kk += 8) {
            uint32_t af[4][4];
            #pragma unroll
            for (int mi = 0; mi < 4; mi++) {
                int r = wr + mi * 16 + g;
                af[mi][0] = As[r    ][kk + q];
                af[mi][1] = As[r + 8][kk + q];
                af[mi][2] = As[r    ][kk + 4 + q];
                af[mi][3] = As[r + 8][kk + 4 + q];
            }
            uint32_t bf[4][2];
            #pragma unroll
            for (int ni = 0; ni < 4; ni++) {
                int cn = wc + ni * 8 + g;
                bf[ni][0] = Bs[kk + q    ][cn];
                bf[ni][1] = Bs[kk + 4 + q][cn];
            }
            #pragma unroll
            for (int mi = 0; mi < 4; mi++)
                #pragma unroll
                for (int ni = 0; ni < 4; ni++) {
                    asm volatile(
                        "mma.sync.aligned.m16n8k8.row.col.f32.tf32.tf32.f32 "
                        "{%0,%1,%2,%3},{%4,%5,%6,%7},{%8,%9},{%0,%1,%2,%3};"
                        : "+f"(acc[mi][ni][0]), "+f"(acc[mi][ni][1]),
                          "+f"(acc[mi][ni][2]), "+f"(acc[mi][ni][3])
                        : "r"(af[mi][0]), "r"(af[mi][1]), "r"(af[mi][2]), "r"(af[mi][3]),
                          "r"(bf[ni][0]), "r"(bf[ni][1]));
                }
        }
        __syncthreads();
    }

    // epilogue: c0,c1 at (row0, 2q..2q+1), c2,c3 at (row0+8, same cols)
    #pragma unroll
    for (int mi = 0; mi < 4; mi++) {
        #pragma unroll
        for (int ni = 0; ni < 4; ni++) {
            int r0 = bm + wr + mi * 16 + g;
            int cn = bn + wc + ni * 8 + 2 * q;
            float v0 = acc[mi][ni][0], v1 = acc[mi][ni][1];
            float v2 = acc[mi][ni][2], v3 = acc[mi][ni][3];
            if (RELU) {
                v0 = fmaxf(v0, 0.0f); v1 = fmaxf(v1, 0.0f);
                v2 = fmaxf(v2, 0.0f); v3 = fmaxf(v3, 0.0f);
            }
            if (ADD) {
                float2 s0 = *(const float2*)(Src + (size_t)r0 * N + cn);
                float2 s1 = *(const float2*)(Src + (size_t)(r0 + 8) * N + cn);
                v0 += s0.x; v1 += s0.y; v2 += s1.x; v3 += s1.y;
            }
            *(float2*)(C + (size_t)r0 * N + cn)       = make_float2(v0, v1);
            *(float2*)(C + (size_t)(r0 + 8) * N + cn) = make_float2(v2, v3);
        }
    }
}

// ---------------- kernel 3: masked multi-head attention + residual ----------------
#define TQ 16
#define TSS 32
__global__ void attn_kernel(const float* __restrict__ qp, const float* __restrict__ kp,
                            const float* __restrict__ vp, const float* __restrict__ qin,
                            const int* __restrict__ qlens, const int* __restrict__ klens,
                            float* __restrict__ res) {
    __shared__ float sc[TQ][513];
    __shared__ float qs[TQ][65];
    __shared__ float kv[TSS][65];

    int b = blockIdx.z, h = blockIdx.y;
    int t0 = blockIdx.x * TQ;
    int tid = threadIdx.x;
    int klen = klens[b];
    int qlen = qlens[b];
    size_t base = ((size_t)b * TT) * DD + h * DHH;

    {
        int e = tid * 4;
        int qi = e / DHH, k = e % DHH;
        float4 v = *(const float4*)(qp + base + (size_t)(t0 + qi) * DD + k);
        qs[qi][k] = v.x; qs[qi][k+1] = v.y; qs[qi][k+2] = v.z; qs[qi][k+3] = v.w;
    }

    int sj = tid & (TSS - 1);
    int qi0 = (tid >> 5) * 2;
    for (int s0 = 0; s0 < TT; s0 += TSS) {
        __syncthreads();
        #pragma unroll
        for (int u = 0; u < 2; u++) {
            int e = (tid + u * 256) * 4;
            int si = e / DHH, k = e % DHH;
            float4 v = *(const float4*)(kp + base + (size_t)(s0 + si) * DD + k);
            kv[si][k] = v.x; kv[si][k+1] = v.y; kv[si][k+2] = v.z; kv[si][k+3] = v.w;
        }
        __syncthreads();
        #pragma unroll
        for (int u = 0; u < 2; u++) {
            int qi = qi0 + u;
            float acc = 0.0f;
            #pragma unroll
            for (int k = 0; k < DHH; k++) acc = fmaf(qs[qi][k], kv[sj][k], acc);
            int s = s0 + sj;
            sc[qi][s] = (s < klen) ? acc * 0.125f : -3.0e38f;
        }
    }
    __syncthreads();

    int warp = tid >> 5, lane = tid & 31;
    for (int r = warp; r < TQ; r += 8) {
        float m = -3.0e38f;
        for (int s = lane; s < TT; s += 32) m = fmaxf(m, sc[r][s]);
        #pragma unroll
        for (int o = 16; o > 0; o >>= 1) m = fmaxf(m, __shfl_xor_sync(0xffffffffu, m, o));
        float sum = 0.0f;
        for (int s = lane; s < TT; s += 32) {
            float e = expf(sc[r][s] - m);
            sc[r][s] = e;
            sum += e;
        }
        #pragma unroll
        for (int o = 16; o > 0; o >>= 1) sum += __shfl_xor_sync(0xffffffffu, sum, o);
        float inv = 1.0f / sum;
        for (int s = lane; s < TT; s += 32) sc[r][s] *= inv;
    }

    int qi = tid >> 4;
    int dk = (tid & 15) * 4;
    float acc0 = 0, acc1 = 0, acc2 = 0, acc3 = 0;
    for (int s0 = 0; s0 < TT; s0 += TSS) {
        __syncthreads();
        #pragma unroll
        for (int u = 0; u < 2; u++) {
            int e = (tid + u * 256) * 4;
            int si = e / DHH, k = e % DHH;
            float4 v = *(const float4*)(vp + base + (size_t)(s0 + si) * DD + k);
            kv[si][k] = v.x; kv[si][k+1] = v.y; kv[si][k+2] = v.z; kv[si][k+3] = v.w;
        }
        __syncthreads();
        #pragma unroll
        for (int s = 0; s < TSS; s++) {
            float a = sc[qi][s0 + s];
            acc0 = fmaf(a, kv[s][dk],     acc0);
            acc1 = fmaf(a, kv[s][dk + 1], acc1);
            acc2 = fmaf(a, kv[s][dk + 2], acc2);
            acc3 = fmaf(a, kv[s][dk + 3], acc3);
        }
    }

    int t = t0 + qi;
    bool valid = (t < qlen);
    size_t off = base + (size_t)t * DD + dk;
    float4 r;
    r.x = qin[off + 0] + (valid ? acc0 : 0.0f);
    r.y = qin[off + 1] + (valid ? acc1 : 0.0f);
    r.z = qin[off + 2] + (valid ? acc2 : 0.0f);
    r.w = qin[off + 3] + (valid ? acc3 : 0.0f);
    *(float4*)(res + off) = r;
}

// ---------------- kernel 4: mean over T ----------------
__global__ void mean_kernel(const float* __restrict__ x, float* __restrict__ out) {
    int d = blockIdx.x * blockDim.x + threadIdx.x;
    int b = blockIdx.y;
    if (d >= DD) return;
    float s = 0.0f;
    const float* p = x + ((size_t)b * TT) * DD + d;
    for (int t = 0; t < TT; t++) s += p[(size_t)t * DD];
    out[b * DD + d] = s * (1.0f / (float)TT);
}

// ---------------- launch ----------------
extern "C" void kernel_launch(void* const* d_in, const int* in_sizes, int n_in,
                              void* d_out, int out_size) {
    const float* queries = (const float*)d_in[0];
    const float* keys    = (const float*)d_in[1];
    const int*   qlens   = (const int*)d_in[2];
    const int*   klens   = (const int*)d_in[3];
    const float* W_Q     = (const float*)d_in[4];
    const float* W_K     = (const float*)d_in[5];
    const float* W_V     = (const float*)d_in[6];
    const float* fw1     = (const float*)d_in[7];
    const float* fw2     = (const float*)d_in[8];
    float* out = (float*)d_out;

    float *qin, *kin, *qp, *kp, *vp, *resb, *hid, *res2;
    cudaGetSymbolAddress((void**)&qin,  g_qin);
    cudaGetSymbolAddress((void**)&kin,  g_kin);
    cudaGetSymbolAddress((void**)&qp,   g_qp);
    cudaGetSymbolAddress((void**)&kp,   g_kp);
    cudaGetSymbolAddress((void**)&vp,   g_vp);
    cudaGetSymbolAddress((void**)&resb, g_res);
    cudaGetSymbolAddress((void**)&hid,  g_hid);
    cudaGetSymbolAddress((void**)&res2, g_res2);

    const int M = BB * TT;          // 32768
    const int n_elem = BB * TT * DD;

    addpe_kernel<<<(n_elem + 255) / 256, 256>>>(queries, keys, qin, kin);

    dim3 gproj(DD / 128, M / 128);
    tf32_gemm_kernel<false, false><<<gproj, 256>>>(qin, W_Q, nullptr, qp, M, DD, DD);
    tf32_gemm_kernel<false, false><<<gproj, 256>>>(kin, W_K, nullptr, kp, M, DD, DD);
    tf32_gemm_kernel<false, false><<<gproj, 256>>>(kp, W_V, nullptr, vp, M, DD, DD);

    dim3 gattn(TT / TQ, HH, BB);
    attn_kernel<<<gattn, 256>>>(qp, kp, vp, qin, qlens, klens, resb);

    dim3 gff1((4 * DD) / 128, M / 128);
    tf32_gemm_kernel<true, false><<<gff1, 256>>>(resb, fw1, nullptr, hid, M, 4 * DD, DD);

    dim3 gff2(DD / 128, M / 128);
    tf32_gemm_kernel<false, true><<<gff2, 256>>>(hid, fw2, resb, res2, M, DD, 4 * DD);

    dim3 gmean(DD / 128, BB);
    mean_kernel<<<gmean, 128>>>(res2, out);
}

// round 3
// speedup vs baseline: 4.5254x; 2.7751x over previous
#include <cuda_runtime.h>
#include <cuda_bf16.h>
#include <math.h>
#include <stdint.h>

// Problem constants
#define BB 64
#define TT 512
#define DD 512
#define HH 8
#define DHH 64

// ---------------- scratch (device globals; allocation-free) ----------------
__device__ float g_qin[BB * TT * DD];
__device__ float g_kin[BB * TT * DD];
__device__ float g_qp [BB * TT * DD];
__device__ float g_kp [BB * TT * DD];
__device__ float g_vp [BB * TT * DD];
__device__ float g_res[BB * TT * DD];
__device__ float g_hid[BB * TT * 4 * DD];
__device__ float g_res2[BB * TT * DD];

__device__ __forceinline__ uint32_t f2tf32(float x) {
    uint32_t r;
    asm("cvt.rna.tf32.f32 %0, %1;" : "=r"(r) : "f"(x));
    return r;
}

// ---------------- kernel 1: positional encoding add ----------------
__global__ void addpe_kernel(const float* __restrict__ q, const float* __restrict__ k,
                             float* __restrict__ qo, float* __restrict__ ko) {
    int idx = blockIdx.x * blockDim.x + threadIdx.x;
    if (idx >= BB * TT * DD) return;
    int d = idx % DD;
    int t = (idx / DD) % TT;
    int j = (d < DD / 2) ? d : d - DD / 2;
    float invf = expf(-(2.0f * (float)j / (float)DD) * 9.210340371976184f); // ln(10000)
    float arg = (float)t * invf;
    float pe = (d < DD / 2) ? cosf(arg) : sinf(arg);
    qo[idx] = q[idx] + pe;
    ko[idx] = k[idx] + pe;
}

// ---------------- TF32 tensor-core GEMM (unchanged from R2) ----------------
template<bool RELU, bool ADD>
__global__ __launch_bounds__(256) void tf32_gemm_kernel(
        const float* __restrict__ A, const float* __restrict__ W,
        const float* __restrict__ Src, float* __restrict__ C,
        int M, int N, int K) {
    const int BM = 128, BN = 128, BK = 32;
    __shared__ uint32_t As[BM][BK + 4];
    __shared__ uint32_t Bs[BK][BN + 4];

    int tid = threadIdx.x;
    int lane = tid & 31;
    int warp = tid >> 5;
    int wr = (warp >> 2) * 64;
    int wc = (warp & 3) * 32;
    int bm = blockIdx.y * BM;
    int bn = blockIdx.x * BN;
    int g = lane >> 2;
    int q = lane & 3;

    float acc[4][4][4];
    #pragma unroll
    for (int mi = 0; mi < 4; mi++)
        #pragma unroll
        for (int ni = 0; ni < 4; ni++)
            #pragma unroll
            for (int r = 0; r < 4; r++) acc[mi][ni][r] = 0.0f;

    for (int k0 = 0; k0 < K; k0 += BK) {
        #pragma unroll
        for (int i = 0; i < 4; i++) {
            int c = tid + i * 256;
            int row = c >> 3;
            int col = (c & 7) * 4;
            float4 v = *(const float4*)(A + (size_t)(bm + row) * K + k0 + col);
            As[row][col + 0] = f2tf32(v.x);
            As[row][col + 1] = f2tf32(v.y);
            As[row][col + 2] = f2tf32(v.z);
            As[row][col + 3] = f2tf32(v.w);
        }
        #pragma unroll
        for (int i = 0; i < 4; i++) {
            int c = tid + i * 256;
            int kr = c >> 5;
            int col = (c & 31) * 4;
            float4 v = *(const float4*)(W + (size_t)(k0 + kr) * N + bn + col);
            Bs[kr][col + 0] = f2tf32(v.x);
            Bs[kr][col + 1] = f2tf32(v.y);
            Bs[kr][col + 2] = f2tf32(v.z);
            Bs[kr][col + 3] = f2tf32(v.w);
        }
        __syncthreads();

        #pragma unroll
        for (int kk = 0; kk < BK; kk += 8) {
            uint32_t af[4][4];
            #pragma unroll
            for (int mi = 0; mi < 4; mi++) {
                int r = wr + mi * 16 + g;
                af[mi][0] = As[r    ][kk + q];
                af[mi][1] = As[r + 8][kk + q];
                af[mi][2] = As[r    ][kk + 4 + q];
                af[mi][3] = As[r + 8][kk + 4 + q];
            }
            uint32_t bf[4][2];
            #pragma unroll
            for (int ni = 0; ni < 4; ni++) {
                int cn = wc + ni * 8 + g;
                bf[ni][0] = Bs[kk + q    ][cn];
                bf[ni][1] = Bs[kk + 4 + q][cn];
            }
            #pragma unroll
            for (int mi = 0; mi < 4; mi++)
                #pragma unroll
                for (int ni = 0; ni < 4; ni++) {
                    asm volatile(
                        "mma.sync.aligned.m16n8k8.row.col.f32.tf32.tf32.f32 "
                        "{%0,%1,%2,%3},{%4,%5,%6,%7},{%8,%9},{%0,%1,%2,%3};"
                        : "+f"(acc[mi][ni][0]), "+f"(acc[mi][ni][1]),
                          "+f"(acc[mi][ni][2]), "+f"(acc[mi][ni][3])
                        : "r"(af[mi][0]), "r"(af[mi][1]), "r"(af[mi][2]), "r"(af[mi][3]),
                          "r"(bf[ni][0]), "r"(bf[ni][1]));
                }
        }
        __syncthreads();
    }

    #pragma unroll
    for (int mi = 0; mi < 4; mi++) {
        #pragma unroll
        for (int ni = 0; ni < 4; ni++) {
            int r0 = bm + wr + mi * 16 + g;
            int cn = bn + wc + ni * 8 + 2 * q;
            float v0 = acc[mi][ni][0], v1 = acc[mi][ni][1];
            float v2 = acc[mi][ni][2], v3 = acc[mi][ni][3];
            if (RELU) {
                v0 = fmaxf(v0, 0.0f); v1 = fmaxf(v1, 0.0f);
                v2 = fmaxf(v2, 0.0f); v3 = fmaxf(v3, 0.0f);
            }
            if (ADD) {
                float2 s0 = *(const float2*)(Src + (size_t)r0 * N + cn);
                float2 s1 = *(const float2*)(Src + (size_t)(r0 + 8) * N + cn);
                v0 += s0.x; v1 += s0.y; v2 += s1.x; v3 += s1.y;
            }
            *(float2*)(C + (size_t)r0 * N + cn)       = make_float2(v0, v1);
            *(float2*)(C + (size_t)(r0 + 8) * N + cn) = make_float2(v2, v3);
        }
    }
}

// ---------------- kernel 3: tf32 flash attention + residual ----------------
// grid (T/128, H, B), 256 threads = 8 warps. Warp = 16 q-rows x full chunk.
#define SC 64
__global__ __launch_bounds__(256) void attn_mma_kernel(
        const float* __restrict__ qp, const float* __restrict__ kp,
        const float* __restrict__ vp, const float* __restrict__ qin,
        const int* __restrict__ qlens, const int* __restrict__ klens,
        float* __restrict__ res) {
    __shared__ uint32_t Ks[SC][68];   // [s][dh], pad 68 -> S B-frag LDS conflict-free
    __shared__ uint32_t Vs[SC][72];   // [s][dh], pad 72 -> AV B-frag LDS conflict-free

    int b = blockIdx.z, h = blockIdx.y;
    int t0 = blockIdx.x * 128;
    int tid = threadIdx.x, lane = tid & 31, warp = tid >> 5;
    int g = lane >> 2, q = lane & 3;
    int klen = klens[b];
    int qlen = qlens[b];
    size_t base = ((size_t)b * TT) * DD + h * DHH;
    int rbase = t0 + warp * 16;

    float O[8][4];
    #pragma unroll
    for (int ni = 0; ni < 8; ni++)
        #pragma unroll
        for (int r = 0; r < 4; r++) O[ni][r] = 0.0f;
    float l0 = 0.0f, l1 = 0.0f;

    if (t0 < qlen) {   // uniform per block; else attn output is all zero
        // Q fragments to registers, scale 1/8 folded in
        uint32_t aQ[8][4];
        {
            const float* q0 = qp + base + (size_t)(rbase + g) * DD;
            const float* q8 = qp + base + (size_t)(rbase + g + 8) * DD;
            #pragma unroll
            for (int kk = 0; kk < 8; kk++) {
                int c = kk * 8 + q;
                aQ[kk][0] = f2tf32(q0[c] * 0.125f);
                aQ[kk][1] = f2tf32(q8[c] * 0.125f);
                aQ[kk][2] = f2tf32(q0[c + 4] * 0.125f);
                aQ[kk][3] = f2tf32(q8[c + 4] * 0.125f);
            }
        }

        float m0 = -1e30f, m1 = -1e30f;
        int nchunks = (klen + SC - 1) / SC;

        for (int ch = 0; ch < nchunks; ch++) {
            int s0 = ch * SC;
            __syncthreads();   // prior-iteration readers done
            // stage K,V chunk (64x64 each): 4 float4 per thread per tensor
            #pragma unroll
            for (int i = 0; i < 4; i++) {
                int c = tid + i * 256;
                int row = c >> 4;
                int col = (c & 15) * 4;
                size_t off = base + (size_t)(s0 + row) * DD + col;
                float4 kv4 = *(const float4*)(kp + off);
                Ks[row][col + 0] = f2tf32(kv4.x);
                Ks[row][col + 1] = f2tf32(kv4.y);
                Ks[row][col + 2] = f2tf32(kv4.z);
                Ks[row][col + 3] = f2tf32(kv4.w);
                float4 vv4 = *(const float4*)(vp + off);
                Vs[row][col + 0] = f2tf32(vv4.x);
                Vs[row][col + 1] = f2tf32(vv4.y);
                Vs[row][col + 2] = f2tf32(vv4.z);
                Vs[row][col + 3] = f2tf32(vv4.w);
            }
            __syncthreads();

            // S = Q @ K^T  (16 x 64 per warp)
            float sacc[8][4];
            #pragma unroll
            for (int ni = 0; ni < 8; ni++)
                #pragma unroll
                for (int r = 0; r < 4; r++) sacc[ni][r] = 0.0f;
            #pragma unroll
            for (int kk = 0; kk < 8; kk++) {
                #pragma unroll
                for (int ni = 0; ni < 8; ni++) {
                    uint32_t b0 = Ks[ni * 8 + g][kk * 8 + q];
                    uint32_t b1 = Ks[ni * 8 + g][kk * 8 + q + 4];
                    asm volatile(
                        "mma.sync.aligned.m16n8k8.row.col.f32.tf32.tf32.f32 "
                        "{%0,%1,%2,%3},{%4,%5,%6,%7},{%8,%9},{%0,%1,%2,%3};"
                        : "+f"(sacc[ni][0]), "+f"(sacc[ni][1]),
                          "+f"(sacc[ni][2]), "+f"(sacc[ni][3])
                        : "r"(aQ[kk][0]), "r"(aQ[kk][1]), "r"(aQ[kk][2]), "r"(aQ[kk][3]),
                          "r"(b0), "r"(b1));
                }
            }

            // mask
            int cb = s0 + 2 * q;
            #pragma unroll
            for (int ni = 0; ni < 8; ni++) {
                if (cb + ni * 8     >= klen) { sacc[ni][0] = -1e30f; sacc[ni][2] = -1e30f; }
                if (cb + ni * 8 + 1 >= klen) { sacc[ni][1] = -1e30f; sacc[ni][3] = -1e30f; }
            }

            // online softmax: row stats (rows g and g+8; full row within warp)
            float mc0 = -1e30f, mc1 = -1e30f;
            #pragma unroll
            for (int ni = 0; ni < 8; ni++) {
                mc0 = fmaxf(mc0, fmaxf(sacc[ni][0], sacc[ni][1]));
                mc1 = fmaxf(mc1, fmaxf(sacc[ni][2], sacc[ni][3]));
            }
            #pragma unroll
            for (int o = 1; o <= 2; o <<= 1) {
                mc0 = fmaxf(mc0, __shfl_xor_sync(0xffffffffu, mc0, o));
                mc1 = fmaxf(mc1, __shfl_xor_sync(0xffffffffu, mc1, o));
            }
            float mn0 = fmaxf(m0, mc0), mn1 = fmaxf(m1, mc1);
            float al0 = __expf(m0 - mn0), al1 = __expf(m1 - mn1);
            m0 = mn0; m1 = mn1;

            float rs0 = 0.0f, rs1 = 0.0f;
            #pragma unroll
            for (int ni = 0; ni < 8; ni++) {
                float p0 = __expf(sacc[ni][0] - m0);
                float p1 = __expf(sacc[ni][1] - m0);
                float p2 = __expf(sacc[ni][2] - m1);
                float p3 = __expf(sacc[ni][3] - m1);
                rs0 += p0 + p1; rs1 += p2 + p3;
                sacc[ni][0] = p0; sacc[ni][1] = p1; sacc[ni][2] = p2; sacc[ni][3] = p3;
            }
            #pragma unroll
            for (int o = 1; o <= 2; o <<= 1) {
                rs0 += __shfl_xor_sync(0xffffffffu, rs0, o);
                rs1 += __shfl_xor_sync(0xffffffffu, rs1, o);
            }
            l0 = l0 * al0 + rs0;
            l1 = l1 * al1 + rs1;
            #pragma unroll
            for (int ni = 0; ni < 8; ni++) {
                O[ni][0] *= al0; O[ni][1] *= al0;
                O[ni][2] *= al1; O[ni][3] *= al1;
            }

            // O += P @ V : redistribute P (C layout -> A layout) via shfl
            int srcA = g * 4 + (q >> 1);
            int srcB = srcA + 2;
            bool odd = (q & 1);
            #pragma unroll
            for (int ks = 0; ks < 8; ks++) {
                float v00 = __shfl_sync(0xffffffffu, sacc[ks][0], srcA);
                float v01 = __shfl_sync(0xffffffffu, sacc[ks][1], srcA);
                float v10 = __shfl_sync(0xffffffffu, sacc[ks][2], srcA);
                float v11 = __shfl_sync(0xffffffffu, sacc[ks][3], srcA);
                float w00 = __shfl_sync(0xffffffffu, sacc[ks][0], srcB);
                float w01 = __shfl_sync(0xffffffffu, sacc[ks][1], srcB);
                float w10 = __shfl_sync(0xffffffffu, sacc[ks][2], srcB);
                float w11 = __shfl_sync(0xffffffffu, sacc[ks][3], srcB);
                uint32_t a0 = f2tf32(odd ? v01 : v00);  // row g,   col ks*8+q
                uint32_t a1 = f2tf32(odd ? v11 : v10);  // row g+8, col ks*8+q
                uint32_t a2 = f2tf32(odd ? w01 : w00);  // row g,   col ks*8+q+4
                uint32_t a3 = f2tf32(odd ? w11 : w10);  // row g+8, col ks*8+q+4
                #pragma unroll
                for (int ni = 0; ni < 8; ni++) {
                    uint32_t b0 = Vs[ks * 8 + q    ][ni * 8 + g];
                    uint32_t b1 = Vs[ks * 8 + q + 4][ni * 8 + g];
                    asm volatile(
                        "mma.sync.aligned.m16n8k8.row.col.f32.tf32.tf32.f32 "
                        "{%0,%1,%2,%3},{%4,%5,%6,%7},{%8,%9},{%0,%1,%2,%3};"
                        : "+f"(O[ni][0]), "+f"(O[ni][1]),
                          "+f"(O[ni][2]), "+f"(O[ni][3])
                        : "r"(a0), "r"(a1), "r"(a2), "r"(a3),
                          "r"(b0), "r"(b1));
                }
            }
        }
    }

    // epilogue: res = qin + (t < qlen ? O / l : 0)
    float inv0 = (l0 > 0.0f) ? 1.0f / l0 : 0.0f;
    float inv1 = (l1 > 0.0f) ? 1.0f / l1 : 0.0f;
    int r0 = rbase + g, r1 = rbase + g + 8;
    float s0f = (r0 < qlen) ? inv0 : 0.0f;
    float s1f = (r1 < qlen) ? inv1 : 0.0f;
    size_t off0 = base + (size_t)r0 * DD + 2 * q;
    size_t off1 = base + (size_t)r1 * DD + 2 * q;
    #pragma unroll
    for (int ni = 0; ni < 8; ni++) {
        float2 i0 = *(const float2*)(qin + off0 + ni * 8);
        float2 i1 = *(const float2*)(qin + off1 + ni * 8);
        float2 o0 = make_float2(i0.x + O[ni][0] * s0f, i0.y + O[ni][1] * s0f);
        float2 o1 = make_float2(i1.x + O[ni][2] * s1f, i1.y + O[ni][3] * s1f);
        *(float2*)(res + off0 + ni * 8) = o0;
        *(float2*)(res + off1 + ni * 8) = o1;
    }
}

// ---------------- kernel 4: mean over T ----------------
__global__ void mean_kernel(const float* __restrict__ x, float* __restrict__ out) {
    int d = blockIdx.x * blockDim.x + threadIdx.x;
    int b = blockIdx.y;
    if (d >= DD) return;
    float s = 0.0f;
    const float* p = x + ((size_t)b * TT) * DD + d;
    for (int t = 0; t < TT; t++) s += p[(size_t)t * DD];
    out[b * DD + d] = s * (1.0f / (float)TT);
}

// ---------------- launch ----------------
extern "C" void kernel_launch(void* const* d_in, const int* in_sizes, int n_in,
                              void* d_out, int out_size) {
    const float* queries = (const float*)d_in[0];
    const float* keys    = (const float*)d_in[1];
    const int*   qlens   = (const int*)d_in[2];
    const int*   klens   = (const int*)d_in[3];
    const float* W_Q     = (const float*)d_in[4];
    const float* W_K     = (const float*)d_in[5];
    const float* W_V     = (const float*)d_in[6];
    const float* fw1     = (const float*)d_in[7];
    const float* fw2     = (const float*)d_in[8];
    float* out = (float*)d_out;

    float *qin, *kin, *qp, *kp, *vp, *resb, *hid, *res2;
    cudaGetSymbolAddress((void**)&qin,  g_qin);
    cudaGetSymbolAddress((void**)&kin,  g_kin);
    cudaGetSymbolAddress((void**)&qp,   g_qp);
    cudaGetSymbolAddress((void**)&kp,   g_kp);
    cudaGetSymbolAddress((void**)&vp,   g_vp);
    cudaGetSymbolAddress((void**)&resb, g_res);
    cudaGetSymbolAddress((void**)&hid,  g_hid);
    cudaGetSymbolAddress((void**)&res2, g_res2);

    const int M = BB * TT;          // 32768
    const int n_elem = BB * TT * DD;

    addpe_kernel<<<(n_elem + 255) / 256, 256>>>(queries, keys, qin, kin);

    dim3 gproj(DD / 128, M / 128);
    tf32_gemm_kernel<false, false><<<gproj, 256>>>(qin, W_Q, nullptr, qp, M, DD, DD);
    tf32_gemm_kernel<false, false><<<gproj, 256>>>(kin, W_K, nullptr, kp, M, DD, DD);
    tf32_gemm_kernel<false, false><<<gproj, 256>>>(kp, W_V, nullptr, vp, M, DD, DD);

    dim3 gattn(TT / 128, HH, BB);
    attn_mma_kernel<<<gattn, 256>>>(qp, kp, vp, qin, qlens, klens, resb);

    dim3 gff1((4 * DD) / 128, M / 128);
    tf32_gemm_kernel<true, false><<<gff1, 256>>>(resb, fw1, nullptr, hid, M, 4 * DD, DD);

    dim3 gff2(DD / 128, M / 128);
    tf32_gemm_kernel<false, true><<<gff2, 256>>>(hid, fw2, resb, res2, M, DD, 4 * DD);

    dim3 gmean(DD / 128, BB);
    mean_kernel<<<gmean, 128>>>(res2, out);
}

// round 6
// speedup vs baseline: 4.6352x; 1.0242x over previous
#include <cuda_runtime.h>
#include <cuda_bf16.h>
#include <math.h>
#include <stdint.h>

// Problem constants
#define BB 64
#define TT 512
#define DD 512
#define HH 8
#define DHH 64

// ---------------- scratch (device globals; allocation-free) ----------------
__device__ float g_qin[BB * TT * DD];
__device__ float g_kin[BB * TT * DD];
__device__ float g_qp [BB * TT * DD];
__device__ float g_kp [BB * TT * DD];
__device__ float g_vp [BB * TT * DD];
__device__ float g_res[BB * TT * DD];
__device__ float g_hid[BB * TT * 4 * DD];
__device__ float g_res2[BB * TT * DD];
// tf32-rounded weight copies
__device__ float g_wq[DD * DD];
__device__ float g_wk[DD * DD];
__device__ float g_wv[DD * DD];
__device__ float g_f1[DD * 4 * DD];
__device__ float g_f2[4 * DD * DD];

__device__ __forceinline__ uint32_t f2tf32(float x) {
    uint32_t r;
    asm("cvt.rna.tf32.f32 %0, %1;" : "=r"(r) : "f"(x));
    return r;
}
__device__ __forceinline__ float tf32r(float x) {
    return __uint_as_float(f2tf32(x));
}

#define CPASYNC16(dst, src) \
    asm volatile("cp.async.cg.shared.global [%0], [%1], 16;" :: "r"(dst), "l"(src))

// ---------------- kernel 0: round weights to tf32 (RNA) ----------------
__global__ void roundw_kernel(const float* __restrict__ src, float* __restrict__ dst, int n) {
    int i = blockIdx.x * blockDim.x + threadIdx.x;
    if (i < n) dst[i] = tf32r(src[i]);
}

// ---------------- kernel 1: positional encoding add (tf32-rounded out) ----------------
__global__ void addpe_kernel(const float* __restrict__ q, const float* __restrict__ k,
                             float* __restrict__ qo, float* __restrict__ ko) {
    int idx = blockIdx.x * blockDim.x + threadIdx.x;
    if (idx >= BB * TT * DD) return;
    int d = idx % DD;
    int t = (idx / DD) % TT;
    int j = (d < DD / 2) ? d : d - DD / 2;
    float invf = expf(-(2.0f * (float)j / (float)DD) * 9.210340371976184f); // ln(10000)
    float arg = (float)t * invf;
    float pe = (d < DD / 2) ? cosf(arg) : sinf(arg);
    qo[idx] = tf32r(q[idx] + pe);
    ko[idx] = tf32r(k[idx] + pe);
}

// ---------------- TF32 GEMM, cp.async double-buffered ----------------
// C = [Src +] [relu](A @ W). Inputs must be pre-rounded to tf32 (raw bits fed to mma).
// TFOUT: round outputs to tf32 for downstream mma consumers.
template<bool RELU, bool ADD, bool TFOUT>
__global__ __launch_bounds__(256) void tf32_gemm_pipe(
        const float* __restrict__ A, const float* __restrict__ W,
        const float* __restrict__ Src, float* __restrict__ C,
        int M, int N, int K) {
    const int BK = 32;
    const int AST = 36, BST = 132;          // padded strides (u32 units)
    const int ASTAGE = 128 * AST, BSTAGE = 32 * BST;
    extern __shared__ uint32_t sm[];
    uint32_t* As = sm;                      // [2][128][36]
    uint32_t* Bs = sm + 2 * ASTAGE;         // [2][32][132]

    int tid = threadIdx.x;
    int lane = tid & 31, warp = tid >> 5;
    int wr = (warp >> 2) * 64, wc = (warp & 3) * 32;
    int bm = blockIdx.y * 128, bn = blockIdx.x * 128;
    int g = lane >> 2, q = lane & 3;

    uint32_t smem_base = (uint32_t)__cvta_generic_to_shared(sm);

    float acc[4][4][4];
    #pragma unroll
    for (int mi = 0; mi < 4; mi++)
        #pragma unroll
        for (int ni = 0; ni < 4; ni++)
            #pragma unroll
            for (int r = 0; r < 4; r++) acc[mi][ni][r] = 0.0f;

    auto stage_load = [&](int k0, int s) {
        uint32_t abase = smem_base + (uint32_t)(s * ASTAGE) * 4u;
        uint32_t bbase = smem_base + (uint32_t)(2 * ASTAGE + s * BSTAGE) * 4u;
        #pragma unroll
        for (int i = 0; i < 4; i++) {
            int c = tid + i * 256;
            int row = c >> 3, col = (c & 7) * 4;
            CPASYNC16(abase + (uint32_t)(row * AST + col) * 4u,
                      A + (size_t)(bm + row) * K + k0 + col);
        }
        #pragma unroll
        for (int i = 0; i < 4; i++) {
            int c = tid + i * 256;
            int kr = c >> 5, col = (c & 31) * 4;
            CPASYNC16(bbase + (uint32_t)(kr * BST + col) * 4u,
                      W + (size_t)(k0 + kr) * N + bn + col);
        }
        asm volatile("cp.async.commit_group;");
    };

    stage_load(0, 0);
    int nk = K / BK;
    for (int it = 0; it < nk; it++) {
        if (it + 1 < nk) {
            stage_load((it + 1) * BK, (it + 1) & 1);
            asm volatile("cp.async.wait_group 1;");
        } else {
            asm volatile("cp.async.wait_group 0;");
        }
        __syncthreads();

        const uint32_t* Ab = As + (it & 1) * ASTAGE;
        const uint32_t* Bb = Bs + (it & 1) * BSTAGE;
        #pragma unroll
        for (int kk = 0; kk < BK; kk += 8) {
            uint32_t af[4][4];
            #pragma unroll
            for (int mi = 0; mi < 4; mi++) {
                int r = wr + mi * 16 + g;
                af[mi][0] = Ab[r * AST + kk + q];
                af[mi][1] = Ab[(r + 8) * AST + kk + q];
                af[mi][2] = Ab[r * AST + kk + 4 + q];
                af[mi][3] = Ab[(r + 8) * AST + kk + 4 + q];
            }
            uint32_t bf[4][2];
            #pragma unroll
            for (int ni = 0; ni < 4; ni++) {
                int cn = wc + ni * 8 + g;
                bf[ni][0] = Bb[(kk + q) * BST + cn];
                bf[ni][1] = Bb[(kk + 4 + q) * BST + cn];
            }
            #pragma unroll
            for (int mi = 0; mi < 4; mi++)
                #pragma unroll
                for (int ni = 0; ni < 4; ni++) {
                    asm volatile(
                        "mma.sync.aligned.m16n8k8.row.col.f32.tf32.tf32.f32 "
                        "{%0,%1,%2,%3},{%4,%5,%6,%7},{%8,%9},{%0,%1,%2,%3};"
                        : "+f"(acc[mi][ni][0]), "+f"(acc[mi][ni][1]),
                          "+f"(acc[mi][ni][2]), "+f"(acc[mi][ni][3])
                        : "r"(af[mi][0]), "r"(af[mi][1]), "r"(af[mi][2]), "r"(af[mi][3]),
                          "r"(bf[ni][0]), "r"(bf[ni][1]));
                }
        }
        __syncthreads();
    }

    #pragma unroll
    for (int mi = 0; mi < 4; mi++) {
        #pragma unroll
        for (int ni = 0; ni < 4; ni++) {
            int r0 = bm + wr + mi * 16 + g;
            int cn = bn + wc + ni * 8 + 2 * q;
            float v0 = acc[mi][ni][0], v1 = acc[mi][ni][1];
            float v2 = acc[mi][ni][2], v3 = acc[mi][ni][3];
            if (RELU) {
                v0 = fmaxf(v0, 0.0f); v1 = fmaxf(v1, 0.0f);
                v2 = fmaxf(v2, 0.0f); v3 = fmaxf(v3, 0.0f);
            }
            if (ADD) {
                float2 s0 = *(const float2*)(Src + (size_t)r0 * N + cn);
                float2 s1 = *(const float2*)(Src + (size_t)(r0 + 8) * N + cn);
                v0 += s0.x; v1 += s0.y; v2 += s1.x; v3 += s1.y;
            }
            if (TFOUT) {
                v0 = tf32r(v0); v1 = tf32r(v1); v2 = tf32r(v2); v3 = tf32r(v3);
            }
            *(float2*)(C + (size_t)r0 * N + cn)       = make_float2(v0, v1);
            *(float2*)(C + (size_t)(r0 + 8) * N + cn) = make_float2(v2, v3);
        }
    }
}

// ---------------- kernel 3: tf32 flash attention + residual ----------------
// grid (T/128, H, B), 256 threads = 8 warps. Warp = 16 q-rows x full chunk.
// kp/vp are pre-rounded tf32 -> raw-bit staging is exact.
#define SC 64
__global__ __launch_bounds__(256) void attn_mma_kernel(
        const float* __restrict__ qp, const float* __restrict__ kp,
        const float* __restrict__ vp, const float* __restrict__ qin,
        const int* __restrict__ qlens, const int* __restrict__ klens,
        float* __restrict__ res) {
    __shared__ uint32_t Ks[SC][68];
    __shared__ uint32_t Vs[SC][72];

    int b = blockIdx.z, h = blockIdx.y;
    int t0 = blockIdx.x * 128;
    int tid = threadIdx.x, lane = tid & 31, warp = tid >> 5;
    int g = lane >> 2, q = lane & 3;
    int klen = klens[b];
    int qlen = qlens[b];
    size_t base = ((size_t)b * TT) * DD + h * DHH;
    int rbase = t0 + warp * 16;

    float O[8][4];
    #pragma unroll
    for (int ni = 0; ni < 8; ni++)
        #pragma unroll
        for (int r = 0; r < 4; r++) O[ni][r] = 0.0f;
    float l0 = 0.0f, l1 = 0.0f;

    if (t0 < qlen) {
        uint32_t aQ[8][4];
        {
            const float* q0 = qp + base + (size_t)(rbase + g) * DD;
            const float* q8 = qp + base + (size_t)(rbase + g + 8) * DD;
            #pragma unroll
            for (int kk = 0; kk < 8; kk++) {
                int c = kk * 8 + q;
                aQ[kk][0] = f2tf32(q0[c] * 0.125f);
                aQ[kk][1] = f2tf32(q8[c] * 0.125f);
                aQ[kk][2] = f2tf32(q0[c + 4] * 0.125f);
                aQ[kk][3] = f2tf32(q8[c + 4] * 0.125f);
            }
        }

        float m0 = -1e30f, m1 = -1e30f;
        int nchunks = (klen + SC - 1) / SC;

        for (int ch = 0; ch < nchunks; ch++) {
            int s0 = ch * SC;
            __syncthreads();
            #pragma unroll
            for (int i = 0; i < 4; i++) {
                int c = tid + i * 256;
                int row = c >> 4;
                int col = (c & 15) * 4;
                size_t off = base + (size_t)(s0 + row) * DD + col;
                float4 kv4 = *(const float4*)(kp + off);
                Ks[row][col + 0] = __float_as_uint(kv4.x);
                Ks[row][col + 1] = __float_as_uint(kv4.y);
                Ks[row][col + 2] = __float_as_uint(kv4.z);
                Ks[row][col + 3] = __float_as_uint(kv4.w);
                float4 vv4 = *(const float4*)(vp + off);
                Vs[row][col + 0] = __float_as_uint(vv4.x);
                Vs[row][col + 1] = __float_as_uint(vv4.y);
                Vs[row][col + 2] = __float_as_uint(vv4.z);
                Vs[row][col + 3] = __float_as_uint(vv4.w);
            }
            __syncthreads();

            float sacc[8][4];
            #pragma unroll
            for (int ni = 0; ni < 8; ni++)
                #pragma unroll
                for (int r = 0; r < 4; r++) sacc[ni][r] = 0.0f;
            #pragma unroll
            for (int kk = 0; kk < 8; kk++) {
                #pragma unroll
                for (int ni = 0; ni < 8; ni++) {
                    uint32_t b0 = Ks[ni * 8 + g][kk * 8 + q];
                    uint32_t b1 = Ks[ni * 8 + g][kk * 8 + q + 4];
                    asm volatile(
                        "mma.sync.aligned.m16n8k8.row.col.f32.tf32.tf32.f32 "
                        "{%0,%1,%2,%3},{%4,%5,%6,%7},{%8,%9},{%0,%1,%2,%3};"
                        : "+f"(sacc[ni][0]), "+f"(sacc[ni][1]),
                          "+f"(sacc[ni][2]), "+f"(sacc[ni][3])
                        : "r"(aQ[kk][0]), "r"(aQ[kk][1]), "r"(aQ[kk][2]), "r"(aQ[kk][3]),
                          "r"(b0), "r"(b1));
                }
            }

            int cb = s0 + 2 * q;
            #pragma unroll
            for (int ni = 0; ni < 8; ni++) {
                if (cb + ni * 8     >= klen) { sacc[ni][0] = -1e30f; sacc[ni][2] = -1e30f; }
                if (cb + ni * 8 + 1 >= klen) { sacc[ni][1] = -1e30f; sacc[ni][3] = -1e30f; }
            }

            float mc0 = -1e30f, mc1 = -1e30f;
            #pragma unroll
            for (int ni = 0; ni < 8; ni++) {
                mc0 = fmaxf(mc0, fmaxf(sacc[ni][0], sacc[ni][1]));
                mc1 = fmaxf(mc1, fmaxf(sacc[ni][2], sacc[ni][3]));
            }
            #pragma unroll
            for (int o = 1; o <= 2; o <<= 1) {
                mc0 = fmaxf(mc0, __shfl_xor_sync(0xffffffffu, mc0, o));
                mc1 = fmaxf(mc1, __shfl_xor_sync(0xffffffffu, mc1, o));
            }
            float mn0 = fmaxf(m0, mc0), mn1 = fmaxf(m1, mc1);
            float al0 = __expf(m0 - mn0), al1 = __expf(m1 - mn1);
            m0 = mn0; m1 = mn1;

            float rs0 = 0.0f, rs1 = 0.0f;
            #pragma unroll
            for (int ni = 0; ni < 8; ni++) {
                float p0 = __expf(sacc[ni][0] - m0);
                float p1 = __expf(sacc[ni][1] - m0);
                float p2 = __expf(sacc[ni][2] - m1);
                float p3 = __expf(sacc[ni][3] - m1);
                rs0 += p0 + p1; rs1 += p2 + p3;
                sacc[ni][0] = p0; sacc[ni][1] = p1; sacc[ni][2] = p2; sacc[ni][3] = p3;
            }
            #pragma unroll
            for (int o = 1; o <= 2; o <<= 1) {
                rs0 += __shfl_xor_sync(0xffffffffu, rs0, o);
                rs1 += __shfl_xor_sync(0xffffffffu, rs1, o);
            }
            l0 = l0 * al0 + rs0;
            l1 = l1 * al1 + rs1;
            #pragma unroll
            for (int ni = 0; ni < 8; ni++) {
                O[ni][0] *= al0; O[ni][1] *= al0;
                O[ni][2] *= al1; O[ni][3] *= al1;
            }

            int srcA = g * 4 + (q >> 1);
            int srcB = srcA + 2;
            bool odd = (q & 1);
            #pragma unroll
            for (int ks = 0; ks < 8; ks++) {
                float v00 = __shfl_sync(0xffffffffu, sacc[ks][0], srcA);
                float v01 = __shfl_sync(0xffffffffu, sacc[ks][1], srcA);
                float v10 = __shfl_sync(0xffffffffu, sacc[ks][2], srcA);
                float v11 = __shfl_sync(0xffffffffu, sacc[ks][3], srcA);
                float w00 = __shfl_sync(0xffffffffu, sacc[ks][0], srcB);
                float w01 = __shfl_sync(0xffffffffu, sacc[ks][1], srcB);
                float w10 = __shfl_sync(0xffffffffu, sacc[ks][2], srcB);
                float w11 = __shfl_sync(0xffffffffu, sacc[ks][3], srcB);
                uint32_t a0 = f2tf32(odd ? v01 : v00);
                uint32_t a1 = f2tf32(odd ? v11 : v10);
                uint32_t a2 = f2tf32(odd ? w01 : w00);
                uint32_t a3 = f2tf32(odd ? w11 : w10);
                #pragma unroll
                for (int ni = 0; ni < 8; ni++) {
                    uint32_t b0 = Vs[ks * 8 + q    ][ni * 8 + g];
                    uint32_t b1 = Vs[ks * 8 + q + 4][ni * 8 + g];
                    asm volatile(
                        "mma.sync.aligned.m16n8k8.row.col.f32.tf32.tf32.f32 "
                        "{%0,%1,%2,%3},{%4,%5,%6,%7},{%8,%9},{%0,%1,%2,%3};"
                        : "+f"(O[ni][0]), "+f"(O[ni][1]),
                          "+f"(O[ni][2]), "+f"(O[ni][3])
                        : "r"(a0), "r"(a1), "r"(a2), "r"(a3),
                          "r"(b0), "r"(b1));
                }
            }
        }
    }

    // epilogue: res = tf32(qin + attnout)  (consumed by FFN1 mma + FFN2 residual)
    float inv0 = (l0 > 0.0f) ? 1.0f / l0 : 0.0f;
    float inv1 = (l1 > 0.0f) ? 1.0f / l1 : 0.0f;
    int r0 = rbase + g, r1 = rbase + g + 8;
    float s0f = (r0 < qlen) ? inv0 : 0.0f;
    float s1f = (r1 < qlen) ? inv1 : 0.0f;
    size_t off0 = base + (size_t)r0 * DD + 2 * q;
    size_t off1 = base + (size_t)r1 * DD + 2 * q;
    #pragma unroll
    for (int ni = 0; ni < 8; ni++) {
        float2 i0 = *(const float2*)(qin + off0 + ni * 8);
        float2 i1 = *(const float2*)(qin + off1 + ni * 8);
        float2 o0 = make_float2(tf32r(i0.x + O[ni][0] * s0f), tf32r(i0.y + O[ni][1] * s0f));
        float2 o1 = make_float2(tf32r(i1.x + O[ni][2] * s1f), tf32r(i1.y + O[ni][3] * s1f));
        *(float2*)(res + off0 + ni * 8) = o0;
        *(float2*)(res + off1 + ni * 8) = o1;
    }
}

// ---------------- kernel 4: mean over T ----------------
__global__ void mean_kernel(const float* __restrict__ x, float* __restrict__ out) {
    int d = blockIdx.x * blockDim.x + threadIdx.x;
    int b = blockIdx.y;
    if (d >= DD) return;
    float s = 0.0f;
    const float* p = x + ((size_t)b * TT) * DD + d;
    for (int t = 0; t < TT; t++) s += p[(size_t)t * DD];
    out[b * DD + d] = s * (1.0f / (float)TT);
}

// ---------------- launch ----------------
extern "C" void kernel_launch(void* const* d_in, const int* in_sizes, int n_in,
                              void* d_out, int out_size) {
    const float* queries = (const float*)d_in[0];
    const float* keys    = (const float*)d_in[1];
    const int*   qlens   = (const int*)d_in[2];
    const int*   klens   = (const int*)d_in[3];
    const float* W_Q     = (const float*)d_in[4];
    const float* W_K     = (const float*)d_in[5];
    const float* W_V     = (const float*)d_in[6];
    const float* fw1     = (const float*)d_in[7];
    const float* fw2     = (const float*)d_in[8];
    float* out = (float*)d_out;

    float *qin, *kin, *qp, *kp, *vp, *resb, *hid, *res2;
    float *wq, *wk, *wv, *f1, *f2;
    cudaGetSymbolAddress((void**)&qin,  g_qin);
    cudaGetSymbolAddress((void**)&kin,  g_kin);
    cudaGetSymbolAddress((void**)&qp,   g_qp);
    cudaGetSymbolAddress((void**)&kp,   g_kp);
    cudaGetSymbolAddress((void**)&vp,   g_vp);
    cudaGetSymbolAddress((void**)&resb, g_res);
    cudaGetSymbolAddress((void**)&hid,  g_hid);
    cudaGetSymbolAddress((void**)&res2, g_res2);
    cudaGetSymbolAddress((void**)&wq,   g_wq);
    cudaGetSymbolAddress((void**)&wk,   g_wk);
    cudaGetSymbolAddress((void**)&wv,   g_wv);
    cudaGetSymbolAddress((void**)&f1,   g_f1);
    cudaGetSymbolAddress((void**)&f2,   g_f2);

    const int M = BB * TT;          // 32768
    const int n_elem = BB * TT * DD;
    const int GEMM_SMEM = (2 * 128 * 36 + 2 * 32 * 132) * 4;  // 70656 B

    cudaFuncSetAttribute(tf32_gemm_pipe<false, false, true>,
                         cudaFuncAttributeMaxDynamicSharedMemorySize, GEMM_SMEM);
    cudaFuncSetAttribute(tf32_gemm_pipe<true, false, true>,
                         cudaFuncAttributeMaxDynamicSharedMemorySize, GEMM_SMEM);
    cudaFuncSetAttribute(tf32_gemm_pipe<false, true, false>,
                         cudaFuncAttributeMaxDynamicSharedMemorySize, GEMM_SMEM);

    // 0. round weights to tf32 once per launch (graph replays it; deterministic)
    roundw_kernel<<<(DD * DD + 255) / 256, 256>>>(W_Q, wq, DD * DD);
    roundw_kernel<<<(DD * DD + 255) / 256, 256>>>(W_K, wk, DD * DD);
    roundw_kernel<<<(DD * DD + 255) / 256, 256>>>(W_V, wv, DD * DD);
    roundw_kernel<<<(DD * 4 * DD + 255) / 256, 256>>>(fw1, f1, DD * 4 * DD);
    roundw_kernel<<<(4 * DD * DD + 255) / 256, 256>>>(fw2, f2, 4 * DD * DD);

    addpe_kernel<<<(n_elem + 255) / 256, 256>>>(queries, keys, qin, kin);

    dim3 gproj(DD / 128, M / 128);
    tf32_gemm_pipe<false, false, true><<<gproj, 256, GEMM_SMEM>>>(qin, wq, nullptr, qp, M, DD, DD);
    tf32_gemm_pipe<false, false, true><<<gproj, 256, GEMM_SMEM>>>(kin, wk, nullptr, kp, M, DD, DD);
    tf32_gemm_pipe<false, false, true><<<gproj, 256, GEMM_SMEM>>>(kp, wv, nullptr, vp, M, DD, DD);

    dim3 gattn(TT / 128, HH, BB);
    attn_mma_kernel<<<gattn, 256>>>(qp, kp, vp, qin, qlens, klens, resb);

    dim3 gff1((4 * DD) / 128, M / 128);
    tf32_gemm_pipe<true, false, true><<<gff1, 256, GEMM_SMEM>>>(resb, f1, nullptr, hid, M, 4 * DD, DD);

    dim3 gff2(DD / 128, M / 128);
    tf32_gemm_pipe<false, true, false><<<gff2, 256, GEMM_SMEM>>>(hid, f2, resb, res2, M, DD, 4 * DD);

    dim3 gmean(DD / 128, BB);
    mean_kernel<<<gmean, 128>>>(res2, out);
}

// round 7
// speedup vs baseline: 5.2082x; 1.1236x over previous
#include <cuda_runtime.h>
#include <cuda_bf16.h>
#include <math.h>
#include <stdint.h>

// Problem constants
#define BB 64
#define TT 512
#define DD 512
#define HH 8
#define DHH 64

// ---------------- scratch (device globals; allocation-free) ----------------
__device__ float g_qin[BB * TT * DD];
__device__ float g_kin[BB * TT * DD];
__device__ float g_qp [BB * TT * DD];
__device__ float g_kp [BB * TT * DD];
__device__ float g_vp [BB * TT * DD];
__device__ float g_res[BB * TT * DD];
__device__ float g_hid[BB * TT * 4 * DD];
__device__ float g_res2[BB * TT * DD];
// tf32-rounded weight copies
__device__ float g_wq[DD * DD];
__device__ float g_wk[DD * DD];
__device__ float g_wv[DD * DD];
__device__ float g_f1[DD * 4 * DD];
__device__ float g_f2[4 * DD * DD];

__device__ __forceinline__ uint32_t f2tf32(float x) {
    uint32_t r;
    asm("cvt.rna.tf32.f32 %0, %1;" : "=r"(r) : "f"(x));
    return r;
}
__device__ __forceinline__ float tf32r(float x) {
    return __uint_as_float(f2tf32(x));
}

#define CPASYNC16(dst, src) \
    asm volatile("cp.async.cg.shared.global [%0], [%1], 16;" :: "r"(dst), "l"(src))

// ---------------- kernel 0: round weights to tf32 (RNA) ----------------
__global__ void roundw_kernel(const float* __restrict__ src, float* __restrict__ dst, int n) {
    int i = blockIdx.x * blockDim.x + threadIdx.x;
    if (i < n) dst[i] = tf32r(src[i]);
}

// ---------------- kernel 1: positional encoding add (tf32-rounded out) ----------------
__global__ void addpe_kernel(const float* __restrict__ q, const float* __restrict__ k,
                             float* __restrict__ qo, float* __restrict__ ko) {
    int idx = blockIdx.x * blockDim.x + threadIdx.x;
    if (idx >= BB * TT * DD) return;
    int d = idx % DD;
    int t = (idx / DD) % TT;
    int j = (d < DD / 2) ? d : d - DD / 2;
    float invf = expf(-(2.0f * (float)j / (float)DD) * 9.210340371976184f); // ln(10000)
    float arg = (float)t * invf;
    float pe = (d < DD / 2) ? cosf(arg) : sinf(arg);
    qo[idx] = tf32r(q[idx] + pe);
    ko[idx] = tf32r(k[idx] + pe);
}

// ---------------- TF32 GEMM v3: 128x256 block, 64x64 warp tile, ldmatrix A ----------------
// C = [Src +] [relu](A @ W). Inputs pre-rounded tf32; raw bits to mma.
template<bool RELU, bool ADD, bool TFOUT>
__global__ __launch_bounds__(256, 1) void tf32_gemm_v3(
        const float* __restrict__ A, const float* __restrict__ W,
        const float* __restrict__ Src, float* __restrict__ C,
        int M, int N, int K) {
    const int BK = 32;
    const int AST = 36, BST = 264;          // strides in u32; 264%32=8 -> conflict-free B
    const int ASTAGE = 128 * AST, BSTAGE = 32 * BST;
    extern __shared__ uint32_t sm[];

    int tid = threadIdx.x;
    int lane = tid & 31, warp = tid >> 5;
    int wr = (warp >> 2) * 64;              // warp row base (2 rows of warps)
    int wc = (warp & 3) * 64;               // warp col base (4 cols of warps)
    int bm = blockIdx.y * 128, bn = blockIdx.x * 256;
    int g = lane >> 2, q = lane & 3;

    uint32_t smem_base = (uint32_t)__cvta_generic_to_shared(sm);

    // ldmatrix lane addressing: four 8x8 b16 mats = 16x8 b32 tile
    int lrow = ((lane >> 3) & 1) * 8 + (lane & 7);   // row-within-16
    int lcol = (lane >> 4) * 4;                      // col half

    float acc[4][8][4];
    #pragma unroll
    for (int mi = 0; mi < 4; mi++)
        #pragma unroll
        for (int ni = 0; ni < 8; ni++)
            #pragma unroll
            for (int r = 0; r < 4; r++) acc[mi][ni][r] = 0.0f;

    auto stage_load = [&](int k0, int s) {
        uint32_t abase = smem_base + (uint32_t)(s * ASTAGE) * 4u;
        uint32_t bbase = smem_base + (uint32_t)(2 * ASTAGE + s * BSTAGE) * 4u;
        #pragma unroll
        for (int i = 0; i < 4; i++) {
            int c = tid + i * 256;
            int row = c >> 3, col = (c & 7) * 4;
            CPASYNC16(abase + (uint32_t)(row * AST + col) * 4u,
                      A + (size_t)(bm + row) * K + k0 + col);
        }
        #pragma unroll
        for (int i = 0; i < 8; i++) {
            int c = tid + i * 256;
            int kr = c >> 6, col = (c & 63) * 4;
            CPASYNC16(bbase + (uint32_t)(kr * BST + col) * 4u,
                      W + (size_t)(k0 + kr) * N + bn + col);
        }
        asm volatile("cp.async.commit_group;");
    };

    stage_load(0, 0);
    int nk = K / BK;
    for (int it = 0; it < nk; it++) {
        if (it + 1 < nk) {
            stage_load((it + 1) * BK, (it + 1) & 1);
            asm volatile("cp.async.wait_group 1;");
        } else {
            asm volatile("cp.async.wait_group 0;");
        }
        __syncthreads();

        uint32_t abuf = smem_base + (uint32_t)((it & 1) * ASTAGE) * 4u;
        const uint32_t* Bb = sm + 2 * ASTAGE + (it & 1) * BSTAGE;
        #pragma unroll
        for (int kk = 0; kk < BK; kk += 8) {
            uint32_t af[4][4];
            #pragma unroll
            for (int mi = 0; mi < 4; mi++) {
                uint32_t addr = abuf +
                    (uint32_t)((wr + mi * 16 + lrow) * AST + kk + lcol) * 4u;
                asm volatile(
                    "ldmatrix.sync.aligned.m8n8.x4.shared.b16 {%0,%1,%2,%3}, [%4];"
                    : "=r"(af[mi][0]), "=r"(af[mi][1]),
                      "=r"(af[mi][2]), "=r"(af[mi][3])
                    : "r"(addr));
            }
            uint32_t bf[8][2];
            #pragma unroll
            for (int ni = 0; ni < 8; ni++) {
                int cn = wc + ni * 8 + g;
                bf[ni][0] = Bb[(kk + q) * BST + cn];
                bf[ni][1] = Bb[(kk + 4 + q) * BST + cn];
            }
            #pragma unroll
            for (int mi = 0; mi < 4; mi++)
                #pragma unroll
                for (int ni = 0; ni < 8; ni++) {
                    asm volatile(
                        "mma.sync.aligned.m16n8k8.row.col.f32.tf32.tf32.f32 "
                        "{%0,%1,%2,%3},{%4,%5,%6,%7},{%8,%9},{%0,%1,%2,%3};"
                        : "+f"(acc[mi][ni][0]), "+f"(acc[mi][ni][1]),
                          "+f"(acc[mi][ni][2]), "+f"(acc[mi][ni][3])
                        : "r"(af[mi][0]), "r"(af[mi][1]), "r"(af[mi][2]), "r"(af[mi][3]),
                          "r"(bf[ni][0]), "r"(bf[ni][1]));
                }
        }
        __syncthreads();
    }

    #pragma unroll
    for (int mi = 0; mi < 4; mi++) {
        #pragma unroll
        for (int ni = 0; ni < 8; ni++) {
            int r0 = bm + wr + mi * 16 + g;
            int cn = bn + wc + ni * 8 + 2 * q;
            float v0 = acc[mi][ni][0], v1 = acc[mi][ni][1];
            float v2 = acc[mi][ni][2], v3 = acc[mi][ni][3];
            if (RELU) {
                v0 = fmaxf(v0, 0.0f); v1 = fmaxf(v1, 0.0f);
                v2 = fmaxf(v2, 0.0f); v3 = fmaxf(v3, 0.0f);
            }
            if (ADD) {
                float2 s0 = *(const float2*)(Src + (size_t)r0 * N + cn);
                float2 s1 = *(const float2*)(Src + (size_t)(r0 + 8) * N + cn);
                v0 += s0.x; v1 += s0.y; v2 += s1.x; v3 += s1.y;
            }
            if (TFOUT) {
                v0 = tf32r(v0); v1 = tf32r(v1); v2 = tf32r(v2); v3 = tf32r(v3);
            }
            *(float2*)(C + (size_t)r0 * N + cn)       = make_float2(v0, v1);
            *(float2*)(C + (size_t)(r0 + 8) * N + cn) = make_float2(v2, v3);
        }
    }
}

// ---------------- kernel 3: tf32 flash attention + residual ----------------
#define SC 64
__global__ __launch_bounds__(256) void attn_mma_kernel(
        const float* __restrict__ qp, const float* __restrict__ kp,
        const float* __restrict__ vp, const float* __restrict__ qin,
        const int* __restrict__ qlens, const int* __restrict__ klens,
        float* __restrict__ res) {
    __shared__ uint32_t Ks[SC][68];
    __shared__ uint32_t Vs[SC][72];

    int b = blockIdx.z, h = blockIdx.y;
    int t0 = blockIdx.x * 128;
    int tid = threadIdx.x, lane = tid & 31, warp = tid >> 5;
    int g = lane >> 2, q = lane & 3;
    int klen = klens[b];
    int qlen = qlens[b];
    size_t base = ((size_t)b * TT) * DD + h * DHH;
    int rbase = t0 + warp * 16;

    float O[8][4];
    #pragma unroll
    for (int ni = 0; ni < 8; ni++)
        #pragma unroll
        for (int r = 0; r < 4; r++) O[ni][r] = 0.0f;
    float l0 = 0.0f, l1 = 0.0f;

    if (t0 < qlen) {
        uint32_t aQ[8][4];
        {
            const float* q0 = qp + base + (size_t)(rbase + g) * DD;
            const float* q8 = qp + base + (size_t)(rbase + g + 8) * DD;
            #pragma unroll
            for (int kk = 0; kk < 8; kk++) {
                int c = kk * 8 + q;
                aQ[kk][0] = f2tf32(q0[c] * 0.125f);
                aQ[kk][1] = f2tf32(q8[c] * 0.125f);
                aQ[kk][2] = f2tf32(q0[c + 4] * 0.125f);
                aQ[kk][3] = f2tf32(q8[c + 4] * 0.125f);
            }
        }

        float m0 = -1e30f, m1 = -1e30f;
        int nchunks = (klen + SC - 1) / SC;

        for (int ch = 0; ch < nchunks; ch++) {
            int s0 = ch * SC;
            __syncthreads();
            #pragma unroll
            for (int i = 0; i < 4; i++) {
                int c = tid + i * 256;
                int row = c >> 4;
                int col = (c & 15) * 4;
                size_t off = base + (size_t)(s0 + row) * DD + col;
                float4 kv4 = *(const float4*)(kp + off);
                Ks[row][col + 0] = __float_as_uint(kv4.x);
                Ks[row][col + 1] = __float_as_uint(kv4.y);
                Ks[row][col + 2] = __float_as_uint(kv4.z);
                Ks[row][col + 3] = __float_as_uint(kv4.w);
                float4 vv4 = *(const float4*)(vp + off);
                Vs[row][col + 0] = __float_as_uint(vv4.x);
                Vs[row][col + 1] = __float_as_uint(vv4.y);
                Vs[row][col + 2] = __float_as_uint(vv4.z);
                Vs[row][col + 3] = __float_as_uint(vv4.w);
            }
            __syncthreads();

            float sacc[8][4];
            #pragma unroll
            for (int ni = 0; ni < 8; ni++)
                #pragma unroll
                for (int r = 0; r < 4; r++) sacc[ni][r] = 0.0f;
            #pragma unroll
            for (int kk = 0; kk < 8; kk++) {
                #pragma unroll
                for (int ni = 0; ni < 8; ni++) {
                    uint32_t b0 = Ks[ni * 8 + g][kk * 8 + q];
                    uint32_t b1 = Ks[ni * 8 + g][kk * 8 + q + 4];
                    asm volatile(
                        "mma.sync.aligned.m16n8k8.row.col.f32.tf32.tf32.f32 "
                        "{%0,%1,%2,%3},{%4,%5,%6,%7},{%8,%9},{%0,%1,%2,%3};"
                        : "+f"(sacc[ni][0]), "+f"(sacc[ni][1]),
                          "+f"(sacc[ni][2]), "+f"(sacc[ni][3])
                        : "r"(aQ[kk][0]), "r"(aQ[kk][1]), "r"(aQ[kk][2]), "r"(aQ[kk][3]),
                          "r"(b0), "r"(b1));
                }
            }

            int cb = s0 + 2 * q;
            #pragma unroll
            for (int ni = 0; ni < 8; ni++) {
                if (cb + ni * 8     >= klen) { sacc[ni][0] = -1e30f; sacc[ni][2] = -1e30f; }
                if (cb + ni * 8 + 1 >= klen) { sacc[ni][1] = -1e30f; sacc[ni][3] = -1e30f; }
            }

            float mc0 = -1e30f, mc1 = -1e30f;
            #pragma unroll
            for (int ni = 0; ni < 8; ni++) {
                mc0 = fmaxf(mc0, fmaxf(sacc[ni][0], sacc[ni][1]));
                mc1 = fmaxf(mc1, fmaxf(sacc[ni][2], sacc[ni][3]));
            }
            #pragma unroll
            for (int o = 1; o <= 2; o <<= 1) {
                mc0 = fmaxf(mc0, __shfl_xor_sync(0xffffffffu, mc0, o));
                mc1 = fmaxf(mc1, __shfl_xor_sync(0xffffffffu, mc1, o));
            }
            float mn0 = fmaxf(m0, mc0), mn1 = fmaxf(m1, mc1);
            float al0 = __expf(m0 - mn0), al1 = __expf(m1 - mn1);
            m0 = mn0; m1 = mn1;

            float rs0 = 0.0f, rs1 = 0.0f;
            #pragma unroll
            for (int ni = 0; ni < 8; ni++) {
                float p0 = __expf(sacc[ni][0] - m0);
                float p1 = __expf(sacc[ni][1] - m0);
                float p2 = __expf(sacc[ni][2] - m1);
                float p3 = __expf(sacc[ni][3] - m1);
                rs0 += p0 + p1; rs1 += p2 + p3;
                sacc[ni][0] = p0; sacc[ni][1] = p1; sacc[ni][2] = p2; sacc[ni][3] = p3;
            }
            #pragma unroll
            for (int o = 1; o <= 2; o <<= 1) {
                rs0 += __shfl_xor_sync(0xffffffffu, rs0, o);
                rs1 += __shfl_xor_sync(0xffffffffu, rs1, o);
            }
            l0 = l0 * al0 + rs0;
            l1 = l1 * al1 + rs1;
            #pragma unroll
            for (int ni = 0; ni < 8; ni++) {
                O[ni][0] *= al0; O[ni][1] *= al0;
                O[ni][2] *= al1; O[ni][3] *= al1;
            }

            int srcA = g * 4 + (q >> 1);
            int srcB = srcA + 2;
            bool odd = (q & 1);
            #pragma unroll
            for (int ks = 0; ks < 8; ks++) {
                float v00 = __shfl_sync(0xffffffffu, sacc[ks][0], srcA);
                float v01 = __shfl_sync(0xffffffffu, sacc[ks][1], srcA);
                float v10 = __shfl_sync(0xffffffffu, sacc[ks][2], srcA);
                float v11 = __shfl_sync(0xffffffffu, sacc[ks][3], srcA);
                float w00 = __shfl_sync(0xffffffffu, sacc[ks][0], srcB);
                float w01 = __shfl_sync(0xffffffffu, sacc[ks][1], srcB);
                float w10 = __shfl_sync(0xffffffffu, sacc[ks][2], srcB);
                float w11 = __shfl_sync(0xffffffffu, sacc[ks][3], srcB);
                uint32_t a0 = f2tf32(odd ? v01 : v00);
                uint32_t a1 = f2tf32(odd ? v11 : v10);
                uint32_t a2 = f2tf32(odd ? w01 : w00);
                uint32_t a3 = f2tf32(odd ? w11 : w10);
                #pragma unroll
                for (int ni = 0; ni < 8; ni++) {
                    uint32_t b0 = Vs[ks * 8 + q    ][ni * 8 + g];
                    uint32_t b1 = Vs[ks * 8 + q + 4][ni * 8 + g];
                    asm volatile(
                        "mma.sync.aligned.m16n8k8.row.col.f32.tf32.tf32.f32 "
                        "{%0,%1,%2,%3},{%4,%5,%6,%7},{%8,%9},{%0,%1,%2,%3};"
                        : "+f"(O[ni][0]), "+f"(O[ni][1]),
                          "+f"(O[ni][2]), "+f"(O[ni][3])
                        : "r"(a0), "r"(a1), "r"(a2), "r"(a3),
                          "r"(b0), "r"(b1));
                }
            }
        }
    }

    float inv0 = (l0 > 0.0f) ? 1.0f / l0 : 0.0f;
    float inv1 = (l1 > 0.0f) ? 1.0f / l1 : 0.0f;
    int r0 = rbase + g, r1 = rbase + g + 8;
    float s0f = (r0 < qlen) ? inv0 : 0.0f;
    float s1f = (r1 < qlen) ? inv1 : 0.0f;
    size_t off0 = base + (size_t)r0 * DD + 2 * q;
    size_t off1 = base + (size_t)r1 * DD + 2 * q;
    #pragma unroll
    for (int ni = 0; ni < 8; ni++) {
        float2 i0 = *(const float2*)(qin + off0 + ni * 8);
        float2 i1 = *(const float2*)(qin + off1 + ni * 8);
        float2 o0 = make_float2(tf32r(i0.x + O[ni][0] * s0f), tf32r(i0.y + O[ni][1] * s0f));
        float2 o1 = make_float2(tf32r(i1.x + O[ni][2] * s1f), tf32r(i1.y + O[ni][3] * s1f));
        *(float2*)(res + off0 + ni * 8) = o0;
        *(float2*)(res + off1 + ni * 8) = o1;
    }
}

// ---------------- kernel 4: mean over T ----------------
__global__ void mean_kernel(const float* __restrict__ x, float* __restrict__ out) {
    int d = blockIdx.x * blockDim.x + threadIdx.x;
    int b = blockIdx.y;
    if (d >= DD) return;
    float s = 0.0f;
    const float* p = x + ((size_t)b * TT) * DD + d;
    for (int t = 0; t < TT; t++) s += p[(size_t)t * DD];
    out[b * DD + d] = s * (1.0f / (float)TT);
}

// ---------------- launch ----------------
extern "C" void kernel_launch(void* const* d_in, const int* in_sizes, int n_in,
                              void* d_out, int out_size) {
    const float* queries = (const float*)d_in[0];
    const float* keys    = (const float*)d_in[1];
    const int*   qlens   = (const int*)d_in[2];
    const int*   klens   = (const int*)d_in[3];
    const float* W_Q     = (const float*)d_in[4];
    const float* W_K     = (const float*)d_in[5];
    const float* W_V     = (const float*)d_in[6];
    const float* fw1     = (const float*)d_in[7];
    const float* fw2     = (const float*)d_in[8];
    float* out = (float*)d_out;

    float *qin, *kin, *qp, *kp, *vp, *resb, *hid, *res2;
    float *wq, *wk, *wv, *f1, *f2;
    cudaGetSymbolAddress((void**)&qin,  g_qin);
    cudaGetSymbolAddress((void**)&kin,  g_kin);
    cudaGetSymbolAddress((void**)&qp,   g_qp);
    cudaGetSymbolAddress((void**)&kp,   g_kp);
    cudaGetSymbolAddress((void**)&vp,   g_vp);
    cudaGetSymbolAddress((void**)&resb, g_res);
    cudaGetSymbolAddress((void**)&hid,  g_hid);
    cudaGetSymbolAddress((void**)&res2, g_res2);
    cudaGetSymbolAddress((void**)&wq,   g_wq);
    cudaGetSymbolAddress((void**)&wk,   g_wk);
    cudaGetSymbolAddress((void**)&wv,   g_wv);
    cudaGetSymbolAddress((void**)&f1,   g_f1);
    cudaGetSymbolAddress((void**)&f2,   g_f2);

    const int M = BB * TT;          // 32768
    const int n_elem = BB * TT * DD;
    const int GEMM_SMEM = (2 * 128 * 36 + 2 * 32 * 264) * 4;  // 104448 B

    cudaFuncSetAttribute(tf32_gemm_v3<false, false, true>,
                         cudaFuncAttributeMaxDynamicSharedMemorySize, GEMM_SMEM);
    cudaFuncSetAttribute(tf32_gemm_v3<true, false, true>,
                         cudaFuncAttributeMaxDynamicSharedMemorySize, GEMM_SMEM);
    cudaFuncSetAttribute(tf32_gemm_v3<false, true, false>,
                         cudaFuncAttributeMaxDynamicSharedMemorySize, GEMM_SMEM);

    // 0. round weights to tf32 once
    roundw_kernel<<<(DD * DD + 255) / 256, 256>>>(W_Q, wq, DD * DD);
    roundw_kernel<<<(DD * DD + 255) / 256, 256>>>(W_K, wk, DD * DD);
    roundw_kernel<<<(DD * DD + 255) / 256, 256>>>(W_V, wv, DD * DD);
    roundw_kernel<<<(DD * 4 * DD + 255) / 256, 256>>>(fw1, f1, DD * 4 * DD);
    roundw_kernel<<<(4 * DD * DD + 255) / 256, 256>>>(fw2, f2, 4 * DD * DD);

    addpe_kernel<<<(n_elem + 255) / 256, 256>>>(queries, keys, qin, kin);

    dim3 gproj(DD / 256, M / 128);
    tf32_gemm_v3<false, false, true><<<gproj, 256, GEMM_SMEM>>>(qin, wq, nullptr, qp, M, DD, DD);
    tf32_gemm_v3<false, false, true><<<gproj, 256, GEMM_SMEM>>>(kin, wk, nullptr, kp, M, DD, DD);
    tf32_gemm_v3<false, false, true><<<gproj, 256, GEMM_SMEM>>>(kp, wv, nullptr, vp, M, DD, DD);

    dim3 gattn(TT / 128, HH, BB);
    attn_mma_kernel<<<gattn, 256>>>(qp, kp, vp, qin, qlens, klens, resb);

    dim3 gff1((4 * DD) / 256, M / 128);
    tf32_gemm_v3<true, false, true><<<gff1, 256, GEMM_SMEM>>>(resb, f1, nullptr, hid, M, 4 * DD, DD);

    dim3 gff2(DD / 256, M / 128);
    tf32_gemm_v3<false, true, false><<<gff2, 256, GEMM_SMEM>>>(hid, f2, resb, res2, M, DD, 4 * DD);

    dim3 gmean(DD / 128, BB);
    mean_kernel<<<gmean, 128>>>(res2, out);
}

// round 8
// speedup vs baseline: 5.2951x; 1.0167x over previous
#include <cuda_runtime.h>
#include <cuda_bf16.h>
#include <math.h>
#include <stdint.h>

// Problem constants
#define BB 64
#define TT 512
#define DD 512
#define HH 8
#define DHH 64

// ---------------- scratch (device globals; allocation-free) ----------------
__device__ float g_qin[BB * TT * DD];
__device__ float g_kin[BB * TT * DD];
__device__ float g_qp [BB * TT * DD];
__device__ float g_kp [BB * TT * DD];
__device__ float g_vp [BB * TT * DD];
__device__ float g_res[BB * TT * DD];
__device__ float g_hid[BB * TT * 4 * DD];
__device__ float g_res2[BB * TT * DD];
// tf32-rounded weight copies
__device__ float g_wq[DD * DD];
__device__ float g_wk[DD * DD];
__device__ float g_wv[DD * DD];
__device__ float g_f1[DD * 4 * DD];
__device__ float g_f2[4 * DD * DD];

__device__ __forceinline__ uint32_t f2tf32(float x) {
    uint32_t r;
    asm("cvt.rna.tf32.f32 %0, %1;" : "=r"(r) : "f"(x));
    return r;
}
__device__ __forceinline__ float tf32r(float x) {
    return __uint_as_float(f2tf32(x));
}

#define CPASYNC16(dst, src) \
    asm volatile("cp.async.cg.shared.global [%0], [%1], 16;" :: "r"(dst), "l"(src))

// ---------------- kernel 0: round all weights to tf32 (single launch) ----------------
__global__ void roundw_all_kernel(const float* __restrict__ wq0, float* __restrict__ wq1,
                                  const float* __restrict__ wk0, float* __restrict__ wk1,
                                  const float* __restrict__ wv0, float* __restrict__ wv1,
                                  const float* __restrict__ f10, float* __restrict__ f11,
                                  const float* __restrict__ f20, float* __restrict__ f21) {
    int i = blockIdx.x * blockDim.x + threadIdx.x;
    if (i < DD * DD) {
        wq1[i] = tf32r(wq0[i]);
        wk1[i] = tf32r(wk0[i]);
        wv1[i] = tf32r(wv0[i]);
    }
    if (i < DD * 4 * DD) {
        f11[i] = tf32r(f10[i]);
        f21[i] = tf32r(f20[i]);
    }
}

// ---------------- kernel 1: positional encoding add (tf32-rounded out) ----------------
__global__ void addpe_kernel(const float* __restrict__ q, const float* __restrict__ k,
                             float* __restrict__ qo, float* __restrict__ ko) {
    int idx = blockIdx.x * blockDim.x + threadIdx.x;
    if (idx >= BB * TT * DD) return;
    int d = idx % DD;
    int t = (idx / DD) % TT;
    int j = (d < DD / 2) ? d : d - DD / 2;
    float invf = expf(-(2.0f * (float)j / (float)DD) * 9.210340371976184f); // ln(10000)
    float arg = (float)t * invf;
    float pe = (d < DD / 2) ? cosf(arg) : sinf(arg);
    qo[idx] = tf32r(q[idx] + pe);
    ko[idx] = tf32r(k[idx] + pe);
}

// ---------------- TF32 GEMM v4: 4-stage cp.async, single barrier per K-tile ----------------
// 128x256 block, 64x64 warp tile, ldmatrix A, conflict-free B (stride 264).
template<bool RELU, bool ADD, bool TFOUT>
__global__ __launch_bounds__(256, 1) void tf32_gemm_v4(
        const float* __restrict__ A, const float* __restrict__ W,
        const float* __restrict__ Src, float* __restrict__ C,
        int M, int N, int K) {
    const int BK = 32;
    const int AST = 36, BST = 264;            // u32 strides; 264%32=8 -> conflict-free B
    const int ASTAGE = 128 * AST, BSTAGE = 32 * BST;
    const int STAGE = ASTAGE + BSTAGE;        // 13056 u32 per stage
    extern __shared__ uint32_t sm[];

    int tid = threadIdx.x;
    int lane = tid & 31, warp = tid >> 5;
    int wr = (warp >> 2) * 64;
    int wc = (warp & 3) * 64;
    int bm = blockIdx.y * 128, bn = blockIdx.x * 256;
    int g = lane >> 2, q = lane & 3;

    uint32_t smem_base = (uint32_t)__cvta_generic_to_shared(sm);

    int lrow = ((lane >> 3) & 1) * 8 + (lane & 7);
    int lcol = (lane >> 4) * 4;

    float acc[4][8][4];
    #pragma unroll
    for (int mi = 0; mi < 4; mi++)
        #pragma unroll
        for (int ni = 0; ni < 8; ni++)
            #pragma unroll
            for (int r = 0; r < 4; r++) acc[mi][ni][r] = 0.0f;

    auto stage_load = [&](int k0, int s) {
        uint32_t abase = smem_base + (uint32_t)(s * STAGE) * 4u;
        uint32_t bbase = abase + (uint32_t)ASTAGE * 4u;
        #pragma unroll
        for (int i = 0; i < 4; i++) {
            int c = tid + i * 256;
            int row = c >> 3, col = (c & 7) * 4;
            CPASYNC16(abase + (uint32_t)(row * AST + col) * 4u,
                      A + (size_t)(bm + row) * K + k0 + col);
        }
        #pragma unroll
        for (int i = 0; i < 8; i++) {
            int c = tid + i * 256;
            int kr = c >> 6, col = (c & 63) * 4;
            CPASYNC16(bbase + (uint32_t)(kr * BST + col) * 4u,
                      W + (size_t)(k0 + kr) * N + bn + col);
        }
        asm volatile("cp.async.commit_group;");
    };

    int nk = K / BK;   // >= 16 for all our shapes
    stage_load(0, 0);
    stage_load(BK, 1);
    stage_load(2 * BK, 2);

    for (int it = 0; it < nk; it++) {
        asm volatile("cp.async.wait_group 2;");
        __syncthreads();   // stage it%4 visible; all warps done computing it-1
        if (it + 3 < nk) stage_load((it + 3) * BK, (it + 3) & 3);
        else asm volatile("cp.async.commit_group;");   // keep group count aligned

        int s = it & 3;
        uint32_t abuf = smem_base + (uint32_t)(s * STAGE) * 4u;
        const uint32_t* Bb = sm + s * STAGE + ASTAGE;
        #pragma unroll
        for (int kk = 0; kk < BK; kk += 8) {
            uint32_t af[4][4];
            #pragma unroll
            for (int mi = 0; mi < 4; mi++) {
                uint32_t addr = abuf +
                    (uint32_t)((wr + mi * 16 + lrow) * AST + kk + lcol) * 4u;
                asm volatile(
                    "ldmatrix.sync.aligned.m8n8.x4.shared.b16 {%0,%1,%2,%3}, [%4];"
                    : "=r"(af[mi][0]), "=r"(af[mi][1]),
                      "=r"(af[mi][2]), "=r"(af[mi][3])
                    : "r"(addr));
            }
            uint32_t bf[8][2];
            #pragma unroll
            for (int ni = 0; ni < 8; ni++) {
                int cn = wc + ni * 8 + g;
                bf[ni][0] = Bb[(kk + q) * BST + cn];
                bf[ni][1] = Bb[(kk + 4 + q) * BST + cn];
            }
            #pragma unroll
            for (int mi = 0; mi < 4; mi++)
                #pragma unroll
                for (int ni = 0; ni < 8; ni++) {
                    asm volatile(
                        "mma.sync.aligned.m16n8k8.row.col.f32.tf32.tf32.f32 "
                        "{%0,%1,%2,%3},{%4,%5,%6,%7},{%8,%9},{%0,%1,%2,%3};"
                        : "+f"(acc[mi][ni][0]), "+f"(acc[mi][ni][1]),
                          "+f"(acc[mi][ni][2]), "+f"(acc[mi][ni][3])
                        : "r"(af[mi][0]), "r"(af[mi][1]), "r"(af[mi][2]), "r"(af[mi][3]),
                          "r"(bf[ni][0]), "r"(bf[ni][1]));
                }
        }
    }

    #pragma unroll
    for (int mi = 0; mi < 4; mi++) {
        #pragma unroll
        for (int ni = 0; ni < 8; ni++) {
            int r0 = bm + wr + mi * 16 + g;
            int cn = bn + wc + ni * 8 + 2 * q;
            float v0 = acc[mi][ni][0], v1 = acc[mi][ni][1];
            float v2 = acc[mi][ni][2], v3 = acc[mi][ni][3];
            if (RELU) {
                v0 = fmaxf(v0, 0.0f); v1 = fmaxf(v1, 0.0f);
                v2 = fmaxf(v2, 0.0f); v3 = fmaxf(v3, 0.0f);
            }
            if (ADD) {
                float2 s0 = *(const float2*)(Src + (size_t)r0 * N + cn);
                float2 s1 = *(const float2*)(Src + (size_t)(r0 + 8) * N + cn);
                v0 += s0.x; v1 += s0.y; v2 += s1.x; v3 += s1.y;
            }
            if (TFOUT) {
                v0 = tf32r(v0); v1 = tf32r(v1); v2 = tf32r(v2); v3 = tf32r(v3);
            }
            *(float2*)(C + (size_t)r0 * N + cn)       = make_float2(v0, v1);
            *(float2*)(C + (size_t)(r0 + 8) * N + cn) = make_float2(v2, v3);
        }
    }
}

// ---------------- kernel 3: tf32 flash attention + residual ----------------
#define SC 64
__global__ __launch_bounds__(256) void attn_mma_kernel(
        const float* __restrict__ qp, const float* __restrict__ kp,
        const float* __restrict__ vp, const float* __restrict__ qin,
        const int* __restrict__ qlens, const int* __restrict__ klens,
        float* __restrict__ res) {
    __shared__ uint32_t Ks[SC][68];
    __shared__ uint32_t Vs[SC][72];

    int b = blockIdx.z, h = blockIdx.y;
    int t0 = blockIdx.x * 128;
    int tid = threadIdx.x, lane = tid & 31, warp = tid >> 5;
    int g = lane >> 2, q = lane & 3;
    int klen = klens[b];
    int qlen = qlens[b];
    size_t base = ((size_t)b * TT) * DD + h * DHH;
    int rbase = t0 + warp * 16;

    float O[8][4];
    #pragma unroll
    for (int ni = 0; ni < 8; ni++)
        #pragma unroll
        for (int r = 0; r < 4; r++) O[ni][r] = 0.0f;
    float l0 = 0.0f, l1 = 0.0f;

    if (t0 < qlen) {
        uint32_t aQ[8][4];
        {
            const float* q0 = qp + base + (size_t)(rbase + g) * DD;
            const float* q8 = qp + base + (size_t)(rbase + g + 8) * DD;
            #pragma unroll
            for (int kk = 0; kk < 8; kk++) {
                int c = kk * 8 + q;
                aQ[kk][0] = f2tf32(q0[c] * 0.125f);
                aQ[kk][1] = f2tf32(q8[c] * 0.125f);
                aQ[kk][2] = f2tf32(q0[c + 4] * 0.125f);
                aQ[kk][3] = f2tf32(q8[c + 4] * 0.125f);
            }
        }

        float m0 = -1e30f, m1 = -1e30f;
        int nchunks = (klen + SC - 1) / SC;

        for (int ch = 0; ch < nchunks; ch++) {
            int s0 = ch * SC;
            __syncthreads();
            #pragma unroll
            for (int i = 0; i < 4; i++) {
                int c = tid + i * 256;
                int row = c >> 4;
                int col = (c & 15) * 4;
                size_t off = base + (size_t)(s0 + row) * DD + col;
                float4 kv4 = *(const float4*)(kp + off);
                Ks[row][col + 0] = __float_as_uint(kv4.x);
                Ks[row][col + 1] = __float_as_uint(kv4.y);
                Ks[row][col + 2] = __float_as_uint(kv4.z);
                Ks[row][col + 3] = __float_as_uint(kv4.w);
                float4 vv4 = *(const float4*)(vp + off);
                Vs[row][col + 0] = __float_as_uint(vv4.x);
                Vs[row][col + 1] = __float_as_uint(vv4.y);
                Vs[row][col + 2] = __float_as_uint(vv4.z);
                Vs[row][col + 3] = __float_as_uint(vv4.w);
            }
            __syncthreads();

            float sacc[8][4];
            #pragma unroll
            for (int ni = 0; ni < 8; ni++)
                #pragma unroll
                for (int r = 0; r < 4; r++) sacc[ni][r] = 0.0f;
            #pragma unroll
            for (int kk = 0; kk < 8; kk++) {
                #pragma unroll
                for (int ni = 0; ni < 8; ni++) {
                    uint32_t b0 = Ks[ni * 8 + g][kk * 8 + q];
                    uint32_t b1 = Ks[ni * 8 + g][kk * 8 + q + 4];
                    asm volatile(
                        "mma.sync.aligned.m16n8k8.row.col.f32.tf32.tf32.f32 "
                        "{%0,%1,%2,%3},{%4,%5,%6,%7},{%8,%9},{%0,%1,%2,%3};"
                        : "+f"(sacc[ni][0]), "+f"(sacc[ni][1]),
                          "+f"(sacc[ni][2]), "+f"(sacc[ni][3])
                        : "r"(aQ[kk][0]), "r"(aQ[kk][1]), "r"(aQ[kk][2]), "r"(aQ[kk][3]),
                          "r"(b0), "r"(b1));
                }
            }

            int cb = s0 + 2 * q;
            #pragma unroll
            for (int ni = 0; ni < 8; ni++) {
                if (cb + ni * 8     >= klen) { sacc[ni][0] = -1e30f; sacc[ni][2] = -1e30f; }
                if (cb + ni * 8 + 1 >= klen) { sacc[ni][1] = -1e30f; sacc[ni][3] = -1e30f; }
            }

            float mc0 = -1e30f, mc1 = -1e30f;
            #pragma unroll
            for (int ni = 0; ni < 8; ni++) {
                mc0 = fmaxf(mc0, fmaxf(sacc[ni][0], sacc[ni][1]));
                mc1 = fmaxf(mc1, fmaxf(sacc[ni][2], sacc[ni][3]));
            }
            #pragma unroll
            for (int o = 1; o <= 2; o <<= 1) {
                mc0 = fmaxf(mc0, __shfl_xor_sync(0xffffffffu, mc0, o));
                mc1 = fmaxf(mc1, __shfl_xor_sync(0xffffffffu, mc1, o));
            }
            float mn0 = fmaxf(m0, mc0), mn1 = fmaxf(m1, mc1);
            float al0 = __expf(m0 - mn0), al1 = __expf(m1 - mn1);
            m0 = mn0; m1 = mn1;

            float rs0 = 0.0f, rs1 = 0.0f;
            #pragma unroll
            for (int ni = 0; ni < 8; ni++) {
                float p0 = __expf(sacc[ni][0] - m0);
                float p1 = __expf(sacc[ni][1] - m0);
                float p2 = __expf(sacc[ni][2] - m1);
                float p3 = __expf(sacc[ni][3] - m1);
                rs0 += p0 + p1; rs1 += p2 + p3;
                sacc[ni][0] = p0; sacc[ni][1] = p1; sacc[ni][2] = p2; sacc[ni][3] = p3;
            }
            #pragma unroll
            for (int o = 1; o <= 2; o <<= 1) {
                rs0 += __shfl_xor_sync(0xffffffffu, rs0, o);
                rs1 += __shfl_xor_sync(0xffffffffu, rs1, o);
            }
            l0 = l0 * al0 + rs0;
            l1 = l1 * al1 + rs1;
            #pragma unroll
            for (int ni = 0; ni < 8; ni++) {
                O[ni][0] *= al0; O[ni][1] *= al0;
                O[ni][2] *= al1; O[ni][3] *= al1;
            }

            int srcA = g * 4 + (q >> 1);
            int srcB = srcA + 2;
            bool odd = (q & 1);
            #pragma unroll
            for (int ks = 0; ks < 8; ks++) {
                float v00 = __shfl_sync(0xffffffffu, sacc[ks][0], srcA);
                float v01 = __shfl_sync(0xffffffffu, sacc[ks][1], srcA);
                float v10 = __shfl_sync(0xffffffffu, sacc[ks][2], srcA);
                float v11 = __shfl_sync(0xffffffffu, sacc[ks][3], srcA);
                float w00 = __shfl_sync(0xffffffffu, sacc[ks][0], srcB);
                float w01 = __shfl_sync(0xffffffffu, sacc[ks][1], srcB);
                float w10 = __shfl_sync(0xffffffffu, sacc[ks][2], srcB);
                float w11 = __shfl_sync(0xffffffffu, sacc[ks][3], srcB);
                uint32_t a0 = f2tf32(odd ? v01 : v00);
                uint32_t a1 = f2tf32(odd ? v11 : v10);
                uint32_t a2 = f2tf32(odd ? w01 : w00);
                uint32_t a3 = f2tf32(odd ? w11 : w10);
                #pragma unroll
                for (int ni = 0; ni < 8; ni++) {
                    uint32_t b0 = Vs[ks * 8 + q    ][ni * 8 + g];
                    uint32_t b1 = Vs[ks * 8 + q + 4][ni * 8 + g];
                    asm volatile(
                        "mma.sync.aligned.m16n8k8.row.col.f32.tf32.tf32.f32 "
                        "{%0,%1,%2,%3},{%4,%5,%6,%7},{%8,%9},{%0,%1,%2,%3};"
                        : "+f"(O[ni][0]), "+f"(O[ni][1]),
                          "+f"(O[ni][2]), "+f"(O[ni][3])
                        : "r"(a0), "r"(a1), "r"(a2), "r"(a3),
                          "r"(b0), "r"(b1));
                }
            }
        }
    }

    float inv0 = (l0 > 0.0f) ? 1.0f / l0 : 0.0f;
    float inv1 = (l1 > 0.0f) ? 1.0f / l1 : 0.0f;
    int r0 = rbase + g, r1 = rbase + g + 8;
    float s0f = (r0 < qlen) ? inv0 : 0.0f;
    float s1f = (r1 < qlen) ? inv1 : 0.0f;
    size_t off0 = base + (size_t)r0 * DD + 2 * q;
    size_t off1 = base + (size_t)r1 * DD + 2 * q;
    #pragma unroll
    for (int ni = 0; ni < 8; ni++) {
        float2 i0 = *(const float2*)(qin + off0 + ni * 8);
        float2 i1 = *(const float2*)(qin + off1 + ni * 8);
        float2 o0 = make_float2(tf32r(i0.x + O[ni][0] * s0f), tf32r(i0.y + O[ni][1] * s0f));
        float2 o1 = make_float2(tf32r(i1.x + O[ni][2] * s1f), tf32r(i1.y + O[ni][3] * s1f));
        *(float2*)(res + off0 + ni * 8) = o0;
        *(float2*)(res + off1 + ni * 8) = o1;
    }
}

// ---------------- kernel 4: mean over T ----------------
__global__ void mean_kernel(const float* __restrict__ x, float* __restrict__ out) {
    int d = blockIdx.x * blockDim.x + threadIdx.x;
    int b = blockIdx.y;
    if (d >= DD) return;
    float s = 0.0f;
    const float* p = x + ((size_t)b * TT) * DD + d;
    for (int t = 0; t < TT; t++) s += p[(size_t)t * DD];
    out[b * DD + d] = s * (1.0f / (float)TT);
}

// ---------------- launch ----------------
extern "C" void kernel_launch(void* const* d_in, const int* in_sizes, int n_in,
                              void* d_out, int out_size) {
    const float* queries = (const float*)d_in[0];
    const float* keys    = (const float*)d_in[1];
    const int*   qlens   = (const int*)d_in[2];
    const int*   klens   = (const int*)d_in[3];
    const float* W_Q     = (const float*)d_in[4];
    const float* W_K     = (const float*)d_in[5];
    const float* W_V     = (const float*)d_in[6];
    const float* fw1     = (const float*)d_in[7];
    const float* fw2     = (const float*)d_in[8];
    float* out = (float*)d_out;

    float *qin, *kin, *qp, *kp, *vp, *resb, *hid, *res2;
    float *wq, *wk, *wv, *f1, *f2;
    cudaGetSymbolAddress((void**)&qin,  g_qin);
    cudaGetSymbolAddress((void**)&kin,  g_kin);
    cudaGetSymbolAddress((void**)&qp,   g_qp);
    cudaGetSymbolAddress((void**)&kp,   g_kp);
    cudaGetSymbolAddress((void**)&vp,   g_vp);
    cudaGetSymbolAddress((void**)&resb, g_res);
    cudaGetSymbolAddress((void**)&hid,  g_hid);
    cudaGetSymbolAddress((void**)&res2, g_res2);
    cudaGetSymbolAddress((void**)&wq,   g_wq);
    cudaGetSymbolAddress((void**)&wk,   g_wk);
    cudaGetSymbolAddress((void**)&wv,   g_wv);
    cudaGetSymbolAddress((void**)&f1,   g_f1);
    cudaGetSymbolAddress((void**)&f2,   g_f2);

    const int M = BB * TT;          // 32768
    const int n_elem = BB * TT * DD;
    const int GEMM_SMEM = 4 * (128 * 36 + 32 * 264) * 4;  // 208896 B

    cudaFuncSetAttribute(tf32_gemm_v4<false, false, true>,
                         cudaFuncAttributeMaxDynamicSharedMemorySize, GEMM_SMEM);
    cudaFuncSetAttribute(tf32_gemm_v4<true, false, true>,
                         cudaFuncAttributeMaxDynamicSharedMemorySize, GEMM_SMEM);
    cudaFuncSetAttribute(tf32_gemm_v4<false, true, false>,
                         cudaFuncAttributeMaxDynamicSharedMemorySize, GEMM_SMEM);

    // 0. round weights to tf32 (one launch)
    roundw_all_kernel<<<(DD * 4 * DD + 255) / 256, 256>>>(
        W_Q, wq, W_K, wk, W_V, wv, fw1, f1, fw2, f2);

    addpe_kernel<<<(n_elem + 255) / 256, 256>>>(queries, keys, qin, kin);

    dim3 gproj(DD / 256, M / 128);
    tf32_gemm_v4<false, false, true><<<gproj, 256, GEMM_SMEM>>>(qin, wq, nullptr, qp, M, DD, DD);
    tf32_gemm_v4<false, false, true><<<gproj, 256, GEMM_SMEM>>>(kin, wk, nullptr, kp, M, DD, DD);
    tf32_gemm_v4<false, false, true><<<gproj, 256, GEMM_SMEM>>>(kp, wv, nullptr, vp, M, DD, DD);

    dim3 gattn(TT / 128, HH, BB);
    attn_mma_kernel<<<gattn, 256>>>(qp, kp, vp, qin, qlens, klens, resb);

    dim3 gff1((4 * DD) / 256, M / 128);
    tf32_gemm_v4<true, false, true><<<gff1, 256, GEMM_SMEM>>>(resb, f1, nullptr, hid, M, 4 * DD, DD);

    dim3 gff2(DD / 256, M / 128);
    tf32_gemm_v4<false, true, false><<<gff2, 256, GEMM_SMEM>>>(hid, f2, resb, res2, M, DD, 4 * DD);

    dim3 gmean(DD / 128, BB);
    mean_kernel<<<gmean, 128>>>(res2, out);
}

// round 10
// speedup vs baseline: 5.9527x; 1.1242x over previous
#include <cuda_runtime.h>
#include <cuda_bf16.h>
#include <math.h>
#include <stdint.h>

// Problem constants
#define BB 64
#define TT 512
#define DD 512
#define HH 8
#define DHH 64

// ---------------- scratch (device globals; allocation-free) ----------------
__device__ float g_qin[BB * TT * DD];
__device__ float g_kin[BB * TT * DD];
__device__ float g_qp [BB * TT * DD];
__device__ float g_kp [BB * TT * DD];
__device__ float g_vp [BB * TT * DD];
__device__ float g_res[BB * TT * DD];
__device__ float g_hid[BB * TT * 4 * DD];
__device__ float g_res2[BB * TT * DD];
// tf32-rounded weight copies
__device__ float g_wq[DD * DD];
__device__ float g_wk[DD * DD];
__device__ float g_wv[DD * DD];
__device__ float g_f1[DD * 4 * DD];
__device__ float g_f2[4 * DD * DD];

__device__ __forceinline__ uint32_t f2tf32(float x) {
    uint32_t r;
    asm("cvt.rna.tf32.f32 %0, %1;" : "=r"(r) : "f"(x));
    return r;
}
__device__ __forceinline__ float tf32r(float x) {
    return __uint_as_float(f2tf32(x));
}

#define CPASYNC16(dst, src) \
    asm volatile("cp.async.cg.shared.global [%0], [%1], 16;" :: "r"(dst), "l"(src))

// ---------------- kernel 0: round all weights to tf32 (single launch) ----------------
__global__ void roundw_all_kernel(const float* __restrict__ wq0, float* __restrict__ wq1,
                                  const float* __restrict__ wk0, float* __restrict__ wk1,
                                  const float* __restrict__ wv0, float* __restrict__ wv1,
                                  const float* __restrict__ f10, float* __restrict__ f11,
                                  const float* __restrict__ f20, float* __restrict__ f21) {
    int i = blockIdx.x * blockDim.x + threadIdx.x;
    if (i < DD * DD) {
        wq1[i] = tf32r(wq0[i]);
        wk1[i] = tf32r(wk0[i]);
        wv1[i] = tf32r(wv0[i]);
    }
    if (i < DD * 4 * DD) {
        f11[i] = tf32r(f10[i]);
        f21[i] = tf32r(f20[i]);
    }
}

// ---------------- kernel 1: positional encoding add (tf32-rounded out) ----------------
__global__ void addpe_kernel(const float* __restrict__ q, const float* __restrict__ k,
                             float* __restrict__ qo, float* __restrict__ ko) {
    int idx = blockIdx.x * blockDim.x + threadIdx.x;
    if (idx >= BB * TT * DD) return;
    int d = idx % DD;
    int t = (idx / DD) % TT;
    int j = (d < DD / 2) ? d : d - DD / 2;
    float invf = expf(-(2.0f * (float)j / (float)DD) * 9.210340371976184f); // ln(10000)
    float arg = (float)t * invf;
    float pe = (d < DD / 2) ? cosf(arg) : sinf(arg);
    qo[idx] = tf32r(q[idx] + pe);
    ko[idx] = tf32r(k[idx] + pe);
}

// ---------------- TF32 GEMM v5: 128x128 block, 64x32 warp tile, 2 CTAs/SM ----------------
// 3-stage cp.async, single barrier per K-tile, ldmatrix A, conflict-free B.
template<bool RELU, bool ADD, bool TFOUT>
__global__ __launch_bounds__(256, 2) void tf32_gemm_v5(
        const float* __restrict__ A, const float* __restrict__ W,
        const float* __restrict__ Src, float* __restrict__ C,
        int M, int N, int K) {
    const int BK = 32;
    const int AST = 36, BST = 136;            // u32 strides; both conflict-free
    const int ASTAGE = 128 * AST, BSTAGE = 32 * BST;
    const int STAGE = ASTAGE + BSTAGE;        // 8960 u32 per stage
    extern __shared__ uint32_t sm[];

    int tid = threadIdx.x;
    int lane = tid & 31, warp = tid >> 5;
    int wr = (warp >> 2) * 64;                // 2 warp-rows
    int wc = (warp & 3) * 32;                 // 4 warp-cols
    int bm = blockIdx.y * 128, bn = blockIdx.x * 128;
    int g = lane >> 2, q = lane & 3;

    uint32_t smem_base = (uint32_t)__cvta_generic_to_shared(sm);

    int lrow = ((lane >> 3) & 1) * 8 + (lane & 7);
    int lcol = (lane >> 4) * 4;

    float acc[4][4][4];
    #pragma unroll
    for (int mi = 0; mi < 4; mi++)
        #pragma unroll
        for (int ni = 0; ni < 4; ni++)
            #pragma unroll
            for (int r = 0; r < 4; r++) acc[mi][ni][r] = 0.0f;

    auto stage_load = [&](int k0, int s) {
        uint32_t abase = smem_base + (uint32_t)(s * STAGE) * 4u;
        uint32_t bbase = abase + (uint32_t)ASTAGE * 4u;
        #pragma unroll
        for (int i = 0; i < 4; i++) {
            int c = tid + i * 256;
            int row = c >> 3, col = (c & 7) * 4;
            CPASYNC16(abase + (uint32_t)(row * AST + col) * 4u,
                      A + (size_t)(bm + row) * K + k0 + col);
        }
        #pragma unroll
        for (int i = 0; i < 4; i++) {
            int c = tid + i * 256;
            int kr = c >> 5, col = (c & 31) * 4;
            CPASYNC16(bbase + (uint32_t)(kr * BST + col) * 4u,
                      W + (size_t)(k0 + kr) * N + bn + col);
        }
        asm volatile("cp.async.commit_group;");
    };

    int nk = K / BK;
    stage_load(0, 0);
    stage_load(BK, 1);

    for (int it = 0; it < nk; it++) {
        asm volatile("cp.async.wait_group 1;");
        __syncthreads();   // stage it%3 visible; all warps done with it-1
        if (it + 2 < nk) stage_load((it + 2) * BK, (it + 2) % 3);
        else asm volatile("cp.async.commit_group;");

        int s = it % 3;
        uint32_t abuf = smem_base + (uint32_t)(s * STAGE) * 4u;
        const uint32_t* Bb = sm + s * STAGE + ASTAGE;
        #pragma unroll
        for (int kk = 0; kk < BK; kk += 8) {
            uint32_t af[4][4];
            #pragma unroll
            for (int mi = 0; mi < 4; mi++) {
                uint32_t addr = abuf +
                    (uint32_t)((wr + mi * 16 + lrow) * AST + kk + lcol) * 4u;
                asm volatile(
                    "ldmatrix.sync.aligned.m8n8.x4.shared.b16 {%0,%1,%2,%3}, [%4];"
                    : "=r"(af[mi][0]), "=r"(af[mi][1]),
                      "=r"(af[mi][2]), "=r"(af[mi][3])
                    : "r"(addr));
            }
            uint32_t bf[4][2];
            #pragma unroll
            for (int ni = 0; ni < 4; ni++) {
                int cn = wc + ni * 8 + g;
                bf[ni][0] = Bb[(kk + q) * BST + cn];
                bf[ni][1] = Bb[(kk + 4 + q) * BST + cn];
            }
            #pragma unroll
            for (int mi = 0; mi < 4; mi++)
                #pragma unroll
                for (int ni = 0; ni < 4; ni++) {
                    asm volatile(
                        "mma.sync.aligned.m16n8k8.row.col.f32.tf32.tf32.f32 "
                        "{%0,%1,%2,%3},{%4,%5,%6,%7},{%8,%9},{%0,%1,%2,%3};"
                        : "+f"(acc[mi][ni][0]), "+f"(acc[mi][ni][1]),
                          "+f"(acc[mi][ni][2]), "+f"(acc[mi][ni][3])
                        : "r"(af[mi][0]), "r"(af[mi][1]), "r"(af[mi][2]), "r"(af[mi][3]),
                          "r"(bf[ni][0]), "r"(bf[ni][1]));
                }
        }
    }

    #pragma unroll
    for (int mi = 0; mi < 4; mi++) {
        #pragma unroll
        for (int ni = 0; ni < 4; ni++) {
            int r0 = bm + wr + mi * 16 + g;
            int cn = bn + wc + ni * 8 + 2 * q;
            float v0 = acc[mi][ni][0], v1 = acc[mi][ni][1];
            float v2 = acc[mi][ni][2], v3 = acc[mi][ni][3];
            if (RELU) {
                v0 = fmaxf(v0, 0.0f); v1 = fmaxf(v1, 0.0f);
                v2 = fmaxf(v2, 0.0f); v3 = fmaxf(v3, 0.0f);
            }
            if (ADD) {
                float2 s0 = *(const float2*)(Src + (size_t)r0 * N + cn);
                float2 s1 = *(const float2*)(Src + (size_t)(r0 + 8) * N + cn);
                v0 += s0.x; v1 += s0.y; v2 += s1.x; v3 += s1.y;
            }
            if (TFOUT) {
                v0 = tf32r(v0); v1 = tf32r(v1); v2 = tf32r(v2); v3 = tf32r(v3);
            }
            *(float2*)(C + (size_t)r0 * N + cn)       = make_float2(v0, v1);
            *(float2*)(C + (size_t)(r0 + 8) * N + cn) = make_float2(v2, v3);
        }
    }
}

// ---------------- kernel 3: tf32 flash attention + residual ----------------
#define SC 64
__global__ __launch_bounds__(256) void attn_mma_kernel(
        const float* __restrict__ qp, const float* __restrict__ kp,
        const float* __restrict__ vp, const float* __restrict__ qin,
        const int* __restrict__ qlens, const int* __restrict__ klens,
        float* __restrict__ res) {
    __shared__ uint32_t Ks[SC][68];
    __shared__ uint32_t Vs[SC][72];

    int b = blockIdx.z, h = blockIdx.y;
    int t0 = blockIdx.x * 128;
    int tid = threadIdx.x, lane = tid & 31, warp = tid >> 5;
    int g = lane >> 2, q = lane & 3;
    int klen = klens[b];
    int qlen = qlens[b];
    size_t base = ((size_t)b * TT) * DD + h * DHH;
    int rbase = t0 + warp * 16;

    float O[8][4];
    #pragma unroll
    for (int ni = 0; ni < 8; ni++)
        #pragma unroll
        for (int r = 0; r < 4; r++) O[ni][r] = 0.0f;
    float l0 = 0.0f, l1 = 0.0f;

    if (t0 < qlen) {
        uint32_t aQ[8][4];
        {
            const float* q0 = qp + base + (size_t)(rbase + g) * DD;
            const float* q8 = qp + base + (size_t)(rbase + g + 8) * DD;
            #pragma unroll
            for (int kk = 0; kk < 8; kk++) {
                int c = kk * 8 + q;
                aQ[kk][0] = f2tf32(q0[c] * 0.125f);
                aQ[kk][1] = f2tf32(q8[c] * 0.125f);
                aQ[kk][2] = f2tf32(q0[c + 4] * 0.125f);
                aQ[kk][3] = f2tf32(q8[c + 4] * 0.125f);
            }
        }

        float m0 = -1e30f, m1 = -1e30f;
        int nchunks = (klen + SC - 1) / SC;

        for (int ch = 0; ch < nchunks; ch++) {
            int s0 = ch * SC;
            __syncthreads();
            #pragma unroll
            for (int i = 0; i < 4; i++) {
                int c = tid + i * 256;
                int row = c >> 4;
                int col = (c & 15) * 4;
                size_t off = base + (size_t)(s0 + row) * DD + col;
                float4 kv4 = *(const float4*)(kp + off);
                Ks[row][col + 0] = __float_as_uint(kv4.x);
                Ks[row][col + 1] = __float_as_uint(kv4.y);
                Ks[row][col + 2] = __float_as_uint(kv4.z);
                Ks[row][col + 3] = __float_as_uint(kv4.w);
                float4 vv4 = *(const float4*)(vp + off);
                Vs[row][col + 0] = __float_as_uint(vv4.x);
                Vs[row][col + 1] = __float_as_uint(vv4.y);
                Vs[row][col + 2] = __float_as_uint(vv4.z);
                Vs[row][col + 3] = __float_as_uint(vv4.w);
            }
            __syncthreads();

            float sacc[8][4];
            #pragma unroll
            for (int ni = 0; ni < 8; ni++)
                #pragma unroll
                for (int r = 0; r < 4; r++) sacc[ni][r] = 0.0f;
            #pragma unroll
            for (int kk = 0; kk < 8; kk++) {
                #pragma unroll
                for (int ni = 0; ni < 8; ni++) {
                    uint32_t b0 = Ks[ni * 8 + g][kk * 8 + q];
                    uint32_t b1 = Ks[ni * 8 + g][kk * 8 + q + 4];
                    asm volatile(
                        "mma.sync.aligned.m16n8k8.row.col.f32.tf32.tf32.f32 "
                        "{%0,%1,%2,%3},{%4,%5,%6,%7},{%8,%9},{%0,%1,%2,%3};"
                        : "+f"(sacc[ni][0]), "+f"(sacc[ni][1]),
                          "+f"(sacc[ni][2]), "+f"(sacc[ni][3])
                        : "r"(aQ[kk][0]), "r"(aQ[kk][1]), "r"(aQ[kk][2]), "r"(aQ[kk][3]),
                          "r"(b0), "r"(b1));
                }
            }

            int cb = s0 + 2 * q;
            #pragma unroll
            for (int ni = 0; ni < 8; ni++) {
                if (cb + ni * 8     >= klen) { sacc[ni][0] = -1e30f; sacc[ni][2] = -1e30f; }
                if (cb + ni * 8 + 1 >= klen) { sacc[ni][1] = -1e30f; sacc[ni][3] = -1e30f; }
            }

            float mc0 = -1e30f, mc1 = -1e30f;
            #pragma unroll
            for (int ni = 0; ni < 8; ni++) {
                mc0 = fmaxf(mc0, fmaxf(sacc[ni][0], sacc[ni][1]));
                mc1 = fmaxf(mc1, fmaxf(sacc[ni][2], sacc[ni][3]));
            }
            #pragma unroll
            for (int o = 1; o <= 2; o <<= 1) {
                mc0 = fmaxf(mc0, __shfl_xor_sync(0xffffffffu, mc0, o));
                mc1 = fmaxf(mc1, __shfl_xor_sync(0xffffffffu, mc1, o));
            }
            float mn0 = fmaxf(m0, mc0), mn1 = fmaxf(m1, mc1);
            float al0 = __expf(m0 - mn0), al1 = __expf(m1 - mn1);
            m0 = mn0; m1 = mn1;

            float rs0 = 0.0f, rs1 = 0.0f;
            #pragma unroll
            for (int ni = 0; ni < 8; ni++) {
                float p0 = __expf(sacc[ni][0] - m0);
                float p1 = __expf(sacc[ni][1] - m0);
                float p2 = __expf(sacc[ni][2] - m1);
                float p3 = __expf(sacc[ni][3] - m1);
                rs0 += p0 + p1; rs1 += p2 + p3;
                sacc[ni][0] = p0; sacc[ni][1] = p1; sacc[ni][2] = p2; sacc[ni][3] = p3;
            }
            #pragma unroll
            for (int o = 1; o <= 2; o <<= 1) {
                rs0 += __shfl_xor_sync(0xffffffffu, rs0, o);
                rs1 += __shfl_xor_sync(0xffffffffu, rs1, o);
            }
            l0 = l0 * al0 + rs0;
            l1 = l1 * al1 + rs1;
            #pragma unroll
            for (int ni = 0; ni < 8; ni++) {
                O[ni][0] *= al0; O[ni][1] *= al0;
                O[ni][2] *= al1; O[ni][3] *= al1;
            }

            int srcA = g * 4 + (q >> 1);
            int srcB = srcA + 2;
            bool odd = (q & 1);
            #pragma unroll
            for (int ks = 0; ks < 8; ks++) {
                float v00 = __shfl_sync(0xffffffffu, sacc[ks][0], srcA);
                float v01 = __shfl_sync(0xffffffffu, sacc[ks][1], srcA);
                float v10 = __shfl_sync(0xffffffffu, sacc[ks][2], srcA);
                float v11 = __shfl_sync(0xffffffffu, sacc[ks][3], srcA);
                float w00 = __shfl_sync(0xffffffffu, sacc[ks][0], srcB);
                float w01 = __shfl_sync(0xffffffffu, sacc[ks][1], srcB);
                float w10 = __shfl_sync(0xffffffffu, sacc[ks][2], srcB);
                float w11 = __shfl_sync(0xffffffffu, sacc[ks][3], srcB);
                uint32_t a0 = f2tf32(odd ? v01 : v00);
                uint32_t a1 = f2tf32(odd ? v11 : v10);
                uint32_t a2 = f2tf32(odd ? w01 : w00);
                uint32_t a3 = f2tf32(odd ? w11 : w10);
                #pragma unroll
                for (int ni = 0; ni < 8; ni++) {
                    uint32_t b0 = Vs[ks * 8 + q    ][ni * 8 + g];
                    uint32_t b1 = Vs[ks * 8 + q + 4][ni * 8 + g];
                    asm volatile(
                        "mma.sync.aligned.m16n8k8.row.col.f32.tf32.tf32.f32 "
                        "{%0,%1,%2,%3},{%4,%5,%6,%7},{%8,%9},{%0,%1,%2,%3};"
                        : "+f"(O[ni][0]), "+f"(O[ni][1]),
                          "+f"(O[ni][2]), "+f"(O[ni][3])
                        : "r"(a0), "r"(a1), "r"(a2), "r"(a3),
                          "r"(b0), "r"(b1));
                }
            }
        }
    }

    float inv0 = (l0 > 0.0f) ? 1.0f / l0 : 0.0f;
    float inv1 = (l1 > 0.0f) ? 1.0f / l1 : 0.0f;
    int r0 = rbase + g, r1 = rbase + g + 8;
    float s0f = (r0 < qlen) ? inv0 : 0.0f;
    float s1f = (r1 < qlen) ? inv1 : 0.0f;
    size_t off0 = base + (size_t)r0 * DD + 2 * q;
    size_t off1 = base + (size_t)r1 * DD + 2 * q;
    #pragma unroll
    for (int ni = 0; ni < 8; ni++) {
        float2 i0 = *(const float2*)(qin + off0 + ni * 8);
        float2 i1 = *(const float2*)(qin + off1 + ni * 8);
        float2 o0 = make_float2(tf32r(i0.x + O[ni][0] * s0f), tf32r(i0.y + O[ni][1] * s0f));
        float2 o1 = make_float2(tf32r(i1.x + O[ni][2] * s1f), tf32r(i1.y + O[ni][3] * s1f));
        *(float2*)(res + off0 + ni * 8) = o0;
        *(float2*)(res + off1 + ni * 8) = o1;
    }
}

// ---------------- kernel 4: mean over T ----------------
__global__ void mean_kernel(const float* __restrict__ x, float* __restrict__ out) {
    int d = blockIdx.x * blockDim.x + threadIdx.x;
    int b = blockIdx.y;
    if (d >= DD) return;
    float s = 0.0f;
    const float* p = x + ((size_t)b * TT) * DD + d;
    for (int t = 0; t < TT; t++) s += p[(size_t)t * DD];
    out[b * DD + d] = s * (1.0f / (float)TT);
}

// ---------------- launch ----------------
extern "C" void kernel_launch(void* const* d_in, const int* in_sizes, int n_in,
                              void* d_out, int out_size) {
    const float* queries = (const float*)d_in[0];
    const float* keys    = (const float*)d_in[1];
    const int*   qlens   = (const int*)d_in[2];
    const int*   klens   = (const int*)d_in[3];
    const float* W_Q     = (const float*)d_in[4];
    const float* W_K     = (const float*)d_in[5];
    const float* W_V     = (const float*)d_in[6];
    const float* fw1     = (const float*)d_in[7];
    const float* fw2     = (const float*)d_in[8];
    float* out = (float*)d_out;

    float *qin, *kin, *qp, *kp, *vp, *resb, *hid, *res2;
    float *wq, *wk, *wv, *f1, *f2;
    cudaGetSymbolAddress((void**)&qin,  g_qin);
    cudaGetSymbolAddress((void**)&kin,  g_kin);
    cudaGetSymbolAddress((void**)&qp,   g_qp);
    cudaGetSymbolAddress((void**)&kp,   g_kp);
    cudaGetSymbolAddress((void**)&vp,   g_vp);
    cudaGetSymbolAddress((void**)&resb, g_res);
    cudaGetSymbolAddress((void**)&hid,  g_hid);
    cudaGetSymbolAddress((void**)&res2, g_res2);
    cudaGetSymbolAddress((void**)&wq,   g_wq);
    cudaGetSymbolAddress((void**)&wk,   g_wk);
    cudaGetSymbolAddress((void**)&wv,   g_wv);
    cudaGetSymbolAddress((void**)&f1,   g_f1);
    cudaGetSymbolAddress((void**)&f2,   g_f2);

    const int M = BB * TT;          // 32768
    const int n_elem = BB * TT * DD;
    const int GEMM_SMEM = 3 * (128 * 36 + 32 * 136) * 4;  // 107520 B

    cudaFuncSetAttribute(tf32_gemm_v5<false, false, true>,
                         cudaFuncAttributeMaxDynamicSharedMemorySize, GEMM_SMEM);
    cudaFuncSetAttribute(tf32_gemm_v5<true, false, true>,
                         cudaFuncAttributeMaxDynamicSharedMemorySize, GEMM_SMEM);
    cudaFuncSetAttribute(tf32_gemm_v5<false, true, false>,
                         cudaFuncAttributeMaxDynamicSharedMemorySize, GEMM_SMEM);

    // 0. round weights to tf32 (one launch)
    roundw_all_kernel<<<(DD * 4 * DD + 255) / 256, 256>>>(
        W_Q, wq, W_K, wk, W_V, wv, fw1, f1, fw2, f2);

    addpe_kernel<<<(n_elem + 255) / 256, 256>>>(queries, keys, qin, kin);

    dim3 gproj(DD / 128, M / 128);
    tf32_gemm_v5<false, false, true><<<gproj, 256, GEMM_SMEM>>>(qin, wq, nullptr, qp, M, DD, DD);
    tf32_gemm_v5<false, false, true><<<gproj, 256, GEMM_SMEM>>>(kin, wk, nullptr, kp, M, DD, DD);
    tf32_gemm_v5<false, false, true><<<gproj, 256, GEMM_SMEM>>>(kp, wv, nullptr, vp, M, DD, DD);

    dim3 gattn(TT / 128, HH, BB);
    attn_mma_kernel<<<gattn, 256>>>(qp, kp, vp, qin, qlens, klens, resb);

    dim3 gff1((4 * DD) / 128, M / 128);
    tf32_gemm_v5<true, false, true><<<gff1, 256, GEMM_SMEM>>>(resb, f1, nullptr, hid, M, 4 * DD, DD);

    dim3 gff2(DD / 128, M / 128);
    tf32_gemm_v5<false, true, false><<<gff2, 256, GEMM_SMEM>>>(hid, f2, resb, res2, M, DD, 4 * DD);

    dim3 gmean(DD / 128, BB);
    mean_kernel<<<gmean, 128>>>(res2, out);
}